// round 13
// baseline (speedup 1.0000x reference)
#include <cuda_runtime.h>
#include <cuda_bf16.h>
#include <math.h>

#define BATCH 2048
#define STEPS 64
#define HID   64
#define NZv   32
#define INZ   32
#define DOUT  8
#define BT    14
#define NTHR  1024
#define NCTA  ((BATCH + BT - 1) / BT)   /* 147 */

// -------- weight scratch (filled by prep_kernel each call) ----
// mma B-fragments, [ntile][ktile][lane] = {b0h,b1h,b0l,b1l} (bf16 hi/lo split)
__device__ uint4  g_W0Frag [32 * 4 * 32];   // [Wv0|Wc0], K=64 (t col in epilogue)
__device__ uint4  g_W1Frag [32 * 8 * 32];   // [Wv1|Wc1], K=128
__device__ uint4  g_Wv2Frag[ 8 * 8 * 32];   // Wv2, K=128
__device__ uint4  g_WcFrag [256 * 8 * 32];  // Wc2, K=128
__device__ float  g_Wi0T [32  * 128];
__device__ float  g_Wi1T [128 * 128];
__device__ float  g_Wi2T [128 * 64];
__device__ float  g_w0t  [256];             // Wx0[o][0]  (t column)
__device__ float  g_b0   [256];             // [bv0 | bc0]
__device__ float  g_b1   [256];             // [bv1 | bc1]
__device__ float  g_WrT  [64 * 8];          // WrT[h][d]

__device__ __forceinline__ unsigned short bf16_hi_u(float v) {
    return __bfloat16_as_ushort(__float2bfloat16(v));
}
__device__ __forceinline__ unsigned short bf16_lo_u(float v) {
    __nv_bfloat16 h = __float2bfloat16(v);
    return __bfloat16_as_ushort(__float2bfloat16(v - __bfloat162float(h)));
}

__global__ void prep_kernel(const float* __restrict__ Wi0, const float* __restrict__ Wi1,
                            const float* __restrict__ Wi2,
                            const float* __restrict__ Wv0, const float* __restrict__ bv0,
                            const float* __restrict__ Wv1, const float* __restrict__ bv1,
                            const float* __restrict__ Wv2,
                            const float* __restrict__ Wc0, const float* __restrict__ bc0,
                            const float* __restrict__ Wc1, const float* __restrict__ bc1,
                            const float* __restrict__ Wc2, const float* __restrict__ Wr) {
    int tid = blockIdx.x * blockDim.x + threadIdx.x;
    int nt  = gridDim.x * blockDim.x;
    // W0 frags (K=64, source cols shifted by 1 for the t column)
    for (int i = tid; i < 32 * 4 * 32; i += nt) {
        int lane = i & 31, kt = (i >> 5) & 3, ntg = i >> 7;
        int o = ntg * 8 + (lane >> 2);
        int k0 = kt * 16 + 2 * (lane & 3);
        const float* row = (o < 128) ? &Wv0[o * 65] : &Wc0[(o - 128) * 65];
        float w00 = row[k0 + 1], w01 = row[k0 + 2];
        float w10 = row[k0 + 9], w11 = row[k0 + 10];
        uint4 f;
        f.x = (unsigned)bf16_hi_u(w00) | ((unsigned)bf16_hi_u(w01) << 16);
        f.y = (unsigned)bf16_hi_u(w10) | ((unsigned)bf16_hi_u(w11) << 16);
        f.z = (unsigned)bf16_lo_u(w00) | ((unsigned)bf16_lo_u(w01) << 16);
        f.w = (unsigned)bf16_lo_u(w10) | ((unsigned)bf16_lo_u(w11) << 16);
        g_W0Frag[i] = f;
    }
    // W1 frags (K=128)
    for (int i = tid; i < 32 * 8 * 32; i += nt) {
        int lane = i & 31, kt = (i >> 5) & 7, ntg = i >> 8;
        int o = ntg * 8 + (lane >> 2);
        int k0 = kt * 16 + 2 * (lane & 3);
        const float* row = (o < 128) ? &Wv1[o * 128] : &Wc1[(o - 128) * 128];
        float w00 = row[k0], w01 = row[k0 + 1], w10 = row[k0 + 8], w11 = row[k0 + 9];
        uint4 f;
        f.x = (unsigned)bf16_hi_u(w00) | ((unsigned)bf16_hi_u(w01) << 16);
        f.y = (unsigned)bf16_hi_u(w10) | ((unsigned)bf16_hi_u(w11) << 16);
        f.z = (unsigned)bf16_lo_u(w00) | ((unsigned)bf16_lo_u(w01) << 16);
        f.w = (unsigned)bf16_lo_u(w10) | ((unsigned)bf16_lo_u(w11) << 16);
        g_W1Frag[i] = f;
    }
    // Wv2 frags (K=128, N=64)
    for (int i = tid; i < 8 * 8 * 32; i += nt) {
        int lane = i & 31, kt = (i >> 5) & 7, ntg = i >> 8;
        int o = ntg * 8 + (lane >> 2);
        int k0 = kt * 16 + 2 * (lane & 3);
        const float* row = &Wv2[o * 128];
        float w00 = row[k0], w01 = row[k0 + 1], w10 = row[k0 + 8], w11 = row[k0 + 9];
        uint4 f;
        f.x = (unsigned)bf16_hi_u(w00) | ((unsigned)bf16_hi_u(w01) << 16);
        f.y = (unsigned)bf16_hi_u(w10) | ((unsigned)bf16_hi_u(w11) << 16);
        f.z = (unsigned)bf16_lo_u(w00) | ((unsigned)bf16_lo_u(w01) << 16);
        f.w = (unsigned)bf16_lo_u(w10) | ((unsigned)bf16_lo_u(w11) << 16);
        g_Wv2Frag[i] = f;
    }
    // Wc2 frags (K=128, N=2048)
    for (int i = tid; i < 256 * 8 * 32; i += nt) {
        int lane = i & 31, kt = (i >> 5) & 7, ntg = i >> 8;
        int n = ntg * 8 + (lane >> 2);
        int k0 = kt * 16 + 2 * (lane & 3);
        const float* wr = Wc2 + (size_t)n * 128;
        float w00 = wr[k0], w01 = wr[k0 + 1], w10 = wr[k0 + 8], w11 = wr[k0 + 9];
        uint4 f;
        f.x = (unsigned)bf16_hi_u(w00) | ((unsigned)bf16_hi_u(w01) << 16);
        f.y = (unsigned)bf16_hi_u(w10) | ((unsigned)bf16_hi_u(w11) << 16);
        f.z = (unsigned)bf16_lo_u(w00) | ((unsigned)bf16_lo_u(w01) << 16);
        f.w = (unsigned)bf16_lo_u(w10) | ((unsigned)bf16_lo_u(w11) << 16);
        g_WcFrag[i] = f;
    }
    for (int i = tid; i < 32 * 128; i += nt) {
        int k = i >> 7, o = i & 127;
        g_Wi0T[i] = Wi0[o * 32 + k];
    }
    for (int i = tid; i < 128 * 128; i += nt) {
        int k = i >> 7, o = i & 127;
        g_Wi1T[i] = Wi1[o * 128 + k];
    }
    for (int i = tid; i < 128 * 64; i += nt) {
        int k = i >> 6, o = i & 63;
        g_Wi2T[i] = Wi2[o * 128 + k];
    }
    for (int o = tid; o < 256; o += nt) {
        const float* row = (o < 128) ? &Wv0[o * 65] : &Wc0[(o - 128) * 65];
        g_w0t[o] = row[0];
        g_b0[o] = (o < 128) ? bv0[o] : bc0[o - 128];
        g_b1[o] = (o < 128) ? bv1[o] : bc1[o - 128];
    }
    for (int i = tid; i < 64 * 8; i += nt) {
        int h = i >> 3, d = i & 7;
        g_WrT[i] = Wr[d * 64 + h];
    }
}

// fast, accurate-enough transcendentals (abs err ~1e-6)
__device__ __forceinline__ float tanh_fast(float x) {
    float e = __expf(2.0f * x);
    return 1.0f - __fdividef(2.0f, 1.0f + e);
}
__device__ __forceinline__ float lipswish(float x) {
    return 0.909f * __fdividef(x, 1.0f + __expf(-x));
}

#define LDSM4(r0, r1, r2, r3, addr) \
    asm volatile("ldmatrix.sync.aligned.m8n8.x4.shared.b16 {%0,%1,%2,%3}, [%4];" \
        : "=r"(r0), "=r"(r1), "=r"(r2), "=r"(r3) : "r"(addr))

#define MMA_BF16(d, a0, a1, a2, a3, b0, b1) \
    asm volatile("mma.sync.aligned.m16n8k16.row.col.f32.bf16.bf16.f32 " \
        "{%0,%1,%2,%3}, {%4,%5,%6,%7}, {%8,%9}, {%0,%1,%2,%3};" \
        : "+f"(d[0]), "+f"(d[1]), "+f"(d[2]), "+f"(d[3]) \
        : "r"(a0), "r"(a1), "r"(a2), "r"(a3), "r"(b0), "r"(b1))

__global__ void __launch_bounds__(NTHR, 1) sde_kernel(
    const float* __restrict__ ts, const float* __restrict__ init_noise,
    const float* __restrict__ bm,
    const float* __restrict__ bi0, const float* __restrict__ bi1, const float* __restrict__ bi2,
    const float* __restrict__ scale_v, const float* __restrict__ bv2,
    const float* __restrict__ scale_c, const float* __restrict__ bc2,
    const float* __restrict__ br, float* __restrict__ out)
{
    __shared__ float y_s[BT][64];                                             // 3584 B
    __shared__ __align__(16) __nv_bfloat16 yhi_s [16][72],  ylo_s [16][72];   // 4608 B
    __shared__ __align__(16) __nv_bfloat16 h1hi_s[16][264], h1lo_s[16][264];  // 16896 B
    __shared__ __align__(16) __nv_bfloat16 hvhi_s[16][136], hvlo_s[16][136];  // 8704 B
    __shared__ __align__(16) __nv_bfloat16 Ahi_s [16][136], Alo_s [16][136];  // 8704 B
    __shared__ float diff_s[64][15];                                          // 3840 B
    __shared__ float bm_s  [16][33];                                          // 2112 B
    // total 48448 B <= 49152 B static limit

    const int tid  = threadIdx.x;
    const int b0g  = blockIdx.x * BT;
    int nb = BATCH - b0g; if (nb > BT) nb = BT;
    const float ts0 = ts[0];

    const int lane = tid & 31;
    const int wrp  = tid >> 5;                 // 0..31
    const int t    = lane & 3;
    const int g    = lane >> 2;
    const int lrow = lane & 15;
    const int kofs = (lane & 16) ? 8 : 0;
    const unsigned aY   = (unsigned)__cvta_generic_to_shared(&yhi_s [0][0]) + (lrow * 72  + kofs) * 2;
    const unsigned aYl  = (unsigned)__cvta_generic_to_shared(&ylo_s [0][0]) + (lrow * 72  + kofs) * 2;
    const unsigned aH1  = (unsigned)__cvta_generic_to_shared(&h1hi_s[0][0]) + (lrow * 264 + kofs) * 2
                          + ((wrp < 16) ? 0 : 256);   // c-warps contract h1 cols [128,256)
    const unsigned aH1l = (unsigned)__cvta_generic_to_shared(&h1lo_s[0][0]) + (lrow * 264 + kofs) * 2
                          + ((wrp < 16) ? 0 : 256);
    const unsigned aHv  = (unsigned)__cvta_generic_to_shared(&hvhi_s[0][0]) + (lrow * 136 + kofs) * 2;
    const unsigned aHvl = (unsigned)__cvta_generic_to_shared(&hvlo_s[0][0]) + (lrow * 136 + kofs) * 2;
    const unsigned aA   = (unsigned)__cvta_generic_to_shared(&Ahi_s [0][0]) + (lrow * 136 + kofs) * 2;
    const unsigned aAl  = (unsigned)__cvta_generic_to_shared(&Alo_s [0][0]) + (lrow * 136 + kofs) * 2;

    // step-invariant per-thread epilogue constants (registers)
    const int oB = wrp * 8 + 2 * t;            // phase B/C columns oB, oB+1
    const float w0t0 = g_w0t[oB], w0t1 = g_w0t[oB + 1];
    const float b00  = g_b0[oB],  b01  = g_b0[oB + 1];
    const float b10  = g_b1[oB],  b11  = g_b1[oB + 1];
    const int oD = (wrp & 7) * 8 + 2 * t;      // phase D columns (warps 0..7)
    const float bv20 = bv2[oD], bv21 = bv2[oD + 1];
    const float sv0  = scale_v[oD], sv1 = scale_v[oD + 1];

    // ---------------- initial MLP: init_noise -> y0 (first 512 threads) ----------------
    {
        float* nbuf = (float*)diff_s;   // [16][32] staging (2048 B <= 3840 B)
        for (int i = tid; i < 16 * 32; i += NTHR) {
            int b = i >> 5, z = i & 31;
            nbuf[i] = (b < nb) ? init_noise[(size_t)(b0g + b) * INZ + z] : 0.0f;
        }
        __syncthreads();
        if (tid < 512) {   // L0: 32 -> 128, relu -> h1 hi/lo (cols 0..127)
            int o = tid & 127, gg = tid >> 7;
            float acc[4];
            float bias = bi0[o];
            #pragma unroll
            for (int j = 0; j < 4; j++) acc[j] = bias;
            for (int k = 0; k < 32; k++) {
                float w = g_Wi0T[k * 128 + o];
                #pragma unroll
                for (int j = 0; j < 4; j++) acc[j] = fmaf(w, nbuf[(gg * 4 + j) * 32 + k], acc[j]);
            }
            #pragma unroll
            for (int j = 0; j < 4; j++) {
                float v = fmaxf(acc[j], 0.0f);
                __nv_bfloat16 h = __float2bfloat16(v);
                h1hi_s[gg * 4 + j][o] = h;
                h1lo_s[gg * 4 + j][o] = __float2bfloat16(v - __bfloat162float(h));
            }
        }
        __syncthreads();
        if (tid < 512) {   // L1: 128 -> 128, relu -> hv hi/lo
            int o = tid & 127, gg = tid >> 7;
            float acc[4];
            float bias = bi1[o];
            #pragma unroll
            for (int j = 0; j < 4; j++) acc[j] = bias;
            for (int k = 0; k < 128; k++) {
                float w = g_Wi1T[k * 128 + o];
                #pragma unroll
                for (int j = 0; j < 4; j++) {
                    float a = __bfloat162float(h1hi_s[gg * 4 + j][k]) +
                              __bfloat162float(h1lo_s[gg * 4 + j][k]);
                    acc[j] = fmaf(w, a, acc[j]);
                }
            }
            #pragma unroll
            for (int j = 0; j < 4; j++) {
                float v = fmaxf(acc[j], 0.0f);
                __nv_bfloat16 h = __float2bfloat16(v);
                hvhi_s[gg * 4 + j][o] = h;
                hvlo_s[gg * 4 + j][o] = __float2bfloat16(v - __bfloat162float(h));
            }
        }
        __syncthreads();
        if (tid < 512) {   // L2: 128 -> 64, identity -> y0 (fp32 + hi/lo)
            int o = tid & 63, gg = tid >> 6;
            float bias = bi2[o];
            float a0 = bias, a1 = bias;
            for (int k = 0; k < 128; k++) {
                float w = g_Wi2T[k * 64 + o];
                float x0 = __bfloat162float(hvhi_s[gg * 2 + 0][k]) + __bfloat162float(hvlo_s[gg * 2 + 0][k]);
                float x1 = __bfloat162float(hvhi_s[gg * 2 + 1][k]) + __bfloat162float(hvlo_s[gg * 2 + 1][k]);
                a0 = fmaf(w, x0, a0);
                a1 = fmaf(w, x1, a1);
            }
            #pragma unroll
            for (int jj = 0; jj < 2; jj++) {
                int b = gg * 2 + jj;
                float v = jj ? a1 : a0;
                if (b < BT) {
                    y_s[b][o] = v;
                    __nv_bfloat16 h = __float2bfloat16(v);
                    yhi_s[b][o] = h;
                    ylo_s[b][o] = __float2bfloat16(v - __bfloat162float(h));
                } else {
                    yhi_s[b][o] = __float2bfloat16(0.0f);
                    ylo_s[b][o] = __float2bfloat16(0.0f);
                }
            }
        }
        __syncthreads();
    }

    // ---------------- time scan ----------------
    for (int step = 0; step < STEPS; step++) {
        // stage noise
        if (tid < BT * 32) {
            int b = tid >> 5, z = tid & 31;
            bm_s[b][z] = bm[(size_t)(b0g + b) * (STEPS * NZv) + step * NZv + z];
        }
        const float tcur = ts0 + (float)step;
        // ---- phase B: layer0 (256 outputs = 32 ntiles, K=64 mma; t/bias in epilogue) ----
        {
            float acc[4] = {0.0f, 0.0f, 0.0f, 0.0f};
            #pragma unroll
            for (int kt = 0; kt < 4; kt++) {
                unsigned ah0, ah1, ah2, ah3, al0, al1, al2, al3;
                LDSM4(ah0, ah1, ah2, ah3, aY  + kt * 32);
                LDSM4(al0, al1, al2, al3, aYl + kt * 32);
                uint4 W = __ldg(&g_W0Frag[(wrp * 4 + kt) * 32 + lane]);
                MMA_BF16(acc, ah0, ah1, ah2, ah3, W.x, W.y);
                MMA_BF16(acc, ah0, ah1, ah2, ah3, W.z, W.w);
                MMA_BF16(acc, al0, al1, al2, al3, W.x, W.y);
            }
            float bia0 = fmaf(w0t0, tcur, b00);
            float bia1 = fmaf(w0t1, tcur, b01);
            float v00 = lipswish(acc[0] + bia0);
            float v01 = lipswish(acc[1] + bia1);
            float v10 = lipswish(acc[2] + bia0);
            float v11 = lipswish(acc[3] + bia1);
            __nv_bfloat16 h00 = __float2bfloat16(v00), h01 = __float2bfloat16(v01);
            __nv_bfloat16 h10 = __float2bfloat16(v10), h11 = __float2bfloat16(v11);
            h1hi_s[g][oB] = h00;          h1lo_s[g][oB] = __float2bfloat16(v00 - __bfloat162float(h00));
            h1hi_s[g][oB + 1] = h01;      h1lo_s[g][oB + 1] = __float2bfloat16(v01 - __bfloat162float(h01));
            h1hi_s[g + 8][oB] = h10;      h1lo_s[g + 8][oB] = __float2bfloat16(v10 - __bfloat162float(h10));
            h1hi_s[g + 8][oB + 1] = h11;  h1lo_s[g + 8][oB + 1] = __float2bfloat16(v11 - __bfloat162float(h11));
        }
        __syncthreads();
        // ---- phase C: layer1 (256 outputs = 32 ntiles, K=128 mma) ----
        {
            float acc[4] = {0.0f, 0.0f, 0.0f, 0.0f};
            #pragma unroll
            for (int kt = 0; kt < 8; kt++) {
                unsigned ah0, ah1, ah2, ah3, al0, al1, al2, al3;
                LDSM4(ah0, ah1, ah2, ah3, aH1  + kt * 32);
                LDSM4(al0, al1, al2, al3, aH1l + kt * 32);
                uint4 W = __ldg(&g_W1Frag[(wrp * 8 + kt) * 32 + lane]);
                MMA_BF16(acc, ah0, ah1, ah2, ah3, W.x, W.y);
                MMA_BF16(acc, ah0, ah1, ah2, ah3, W.z, W.w);
                MMA_BF16(acc, al0, al1, al2, al3, W.x, W.y);
            }
            float v00 = lipswish(acc[0] + b10);
            float v01 = lipswish(acc[1] + b11);
            float v10 = lipswish(acc[2] + b10);
            float v11 = lipswish(acc[3] + b11);
            __nv_bfloat16 h00 = __float2bfloat16(v00), h01 = __float2bfloat16(v01);
            __nv_bfloat16 h10 = __float2bfloat16(v10), h11 = __float2bfloat16(v11);
            if (wrp < 16) {   // v-half -> hv  (o in [0,128))
                hvhi_s[g][oB] = h00;          hvlo_s[g][oB] = __float2bfloat16(v00 - __bfloat162float(h00));
                hvhi_s[g][oB + 1] = h01;      hvlo_s[g][oB + 1] = __float2bfloat16(v01 - __bfloat162float(h01));
                hvhi_s[g + 8][oB] = h10;      hvlo_s[g + 8][oB] = __float2bfloat16(v10 - __bfloat162float(h10));
                hvhi_s[g + 8][oB + 1] = h11;  hvlo_s[g + 8][oB + 1] = __float2bfloat16(v11 - __bfloat162float(h11));
            } else {          // c-half -> A (k = o-128)
                int k0 = oB - 128, k1 = k0 + 1;
                Ahi_s[g][k0] = h00;       Alo_s[g][k0] = __float2bfloat16(v00 - __bfloat162float(h00));
                Ahi_s[g][k1] = h01;       Alo_s[g][k1] = __float2bfloat16(v01 - __bfloat162float(h01));
                Ahi_s[g + 8][k0] = h10;   Alo_s[g + 8][k0] = __float2bfloat16(v10 - __bfloat162float(h10));
                Ahi_s[g + 8][k1] = h11;   Alo_s[g + 8][k1] = __float2bfloat16(v11 - __bfloat162float(h11));
            }
        }
        __syncthreads();
        // ---- phase D: drift head (64 outputs, K=128 mma), warps 0..7; y in place ----
        if (wrp < 8) {
            float acc[4] = {0.0f, 0.0f, 0.0f, 0.0f};
            #pragma unroll
            for (int kt = 0; kt < 8; kt++) {
                unsigned ah0, ah1, ah2, ah3, al0, al1, al2, al3;
                LDSM4(ah0, ah1, ah2, ah3, aHv  + kt * 32);
                LDSM4(al0, al1, al2, al3, aHvl + kt * 32);
                uint4 W = __ldg(&g_Wv2Frag[(wrp * 8 + kt) * 32 + lane]);
                MMA_BF16(acc, ah0, ah1, ah2, ah3, W.x, W.y);
                MMA_BF16(acc, ah0, ah1, ah2, ah3, W.z, W.w);
                MMA_BF16(acc, al0, al1, al2, al3, W.x, W.y);
            }
            if (g < BT) {
                y_s[g][oD]     += sv0 * tanh_fast(acc[0] + bv20);
                y_s[g][oD + 1] += sv1 * tanh_fast(acc[1] + bv21);
            }
            if (g + 8 < BT) {
                y_s[g + 8][oD]     += sv0 * tanh_fast(acc[2] + bv20);
                y_s[g + 8][oD + 1] += sv1 * tanh_fast(acc[3] + bv21);
            }
        }
        // ---- phase E: controlled field mma; warp owns h pair (2*wrp, 2*wrp+1) ----
        {
            const int h0 = wrp * 2;
            float acc[2][4][4];
            #pragma unroll
            for (int hp = 0; hp < 2; hp++)
                #pragma unroll
                for (int q = 0; q < 4; q++)
                    #pragma unroll
                    for (int r = 0; r < 4; r++) acc[hp][q][r] = 0.0f;
            #pragma unroll
            for (int kt = 0; kt < 8; kt++) {
                unsigned ah0, ah1, ah2, ah3, al0, al1, al2, al3;
                LDSM4(ah0, ah1, ah2, ah3, aA  + kt * 32);
                LDSM4(al0, al1, al2, al3, aAl + kt * 32);
                #pragma unroll
                for (int hp = 0; hp < 2; hp++) {
                    #pragma unroll
                    for (int q = 0; q < 4; q++) {
                        uint4 W = __ldcg(&g_WcFrag[((((h0 + hp) * 4 + q) * 8) + kt) * 32 + lane]);
                        MMA_BF16(acc[hp][q], ah0, ah1, ah2, ah3, W.x, W.y);
                        MMA_BF16(acc[hp][q], ah0, ah1, ah2, ah3, W.z, W.w);
                        MMA_BF16(acc[hp][q], al0, al1, al2, al3, W.x, W.y);
                    }
                }
            }
            #pragma unroll
            for (int hp = 0; hp < 2; hp++) {
                float s0 = 0.0f, s1 = 0.0f;
                #pragma unroll
                for (int q = 0; q < 4; q++) {
                    int n0 = ((h0 + hp) * 4 + q) * 8 + 2 * t;
                    float2 sc = __ldg((const float2*)&scale_c[n0]);
                    float2 bc = __ldg((const float2*)&bc2[n0]);
                    int nz0 = n0 & 31;
                    float t0 = sc.x * tanh_fast(acc[hp][q][0] + bc.x);
                    float t1 = sc.y * tanh_fast(acc[hp][q][1] + bc.y);
                    float t2 = sc.x * tanh_fast(acc[hp][q][2] + bc.x);
                    float t3 = sc.y * tanh_fast(acc[hp][q][3] + bc.y);
                    s0 = fmaf(t0, bm_s[g][nz0],     fmaf(t1, bm_s[g][nz0 + 1],     s0));
                    s1 = fmaf(t2, bm_s[g + 8][nz0], fmaf(t3, bm_s[g + 8][nz0 + 1], s1));
                }
                s0 += __shfl_xor_sync(0xffffffffu, s0, 1);
                s0 += __shfl_xor_sync(0xffffffffu, s0, 2);
                s1 += __shfl_xor_sync(0xffffffffu, s1, 1);
                s1 += __shfl_xor_sync(0xffffffffu, s1, 2);
                if (t == 0) {
                    int h = h0 + hp;
                    diff_s[h][g] = s0;
                    if (g < 6) diff_s[h][g + 8] = s1;
                }
            }
        }
        __syncthreads();
        // ---- phase F: y += diff (fp32 + bf16 hi/lo refresh) ----
        if (tid < BT * 64) {
            int b = tid >> 6, h = tid & 63;
            float v = y_s[b][h] + diff_s[h][b];
            y_s[b][h] = v;
            __nv_bfloat16 hh = __float2bfloat16(v);
            yhi_s[b][h] = hh;
            ylo_s[b][h] = __float2bfloat16(v - __bfloat162float(hh));
        }
        __syncthreads();
        // ---- readout: out[b, step, :] = y @ Wr^T + br ----
        if (tid < BT * DOUT) {
            int b = tid >> 3, d = tid & 7;
            if (b < nb) {
                float acc = br[d];
                #pragma unroll 8
                for (int h = 0; h < 64; h++)
                    acc = fmaf(y_s[b][h], g_WrT[h * 8 + d], acc);
                out[(size_t)(b0g + b) * (STEPS * DOUT) + step * DOUT + d] = acc;
            }
        }
    }
}

extern "C" void kernel_launch(void* const* d_in, const int* in_sizes, int n_in,
                              void* d_out, int out_size) {
    (void)in_sizes; (void)n_in; (void)out_size;
    const float* ts         = (const float*)d_in[0];
    const float* init_noise = (const float*)d_in[1];
    const float* bm         = (const float*)d_in[2];
    const float* Wi0        = (const float*)d_in[3];
    const float* bi0        = (const float*)d_in[4];
    const float* Wi1        = (const float*)d_in[5];
    const float* bi1        = (const float*)d_in[6];
    const float* Wi2        = (const float*)d_in[7];
    const float* bi2        = (const float*)d_in[8];
    const float* scale_v    = (const float*)d_in[9];
    const float* Wv0        = (const float*)d_in[10];
    const float* bv0        = (const float*)d_in[11];
    const float* Wv1        = (const float*)d_in[12];
    const float* bv1        = (const float*)d_in[13];
    const float* Wv2        = (const float*)d_in[14];
    const float* bv2        = (const float*)d_in[15];
    const float* scale_c    = (const float*)d_in[16];
    const float* Wc0        = (const float*)d_in[17];
    const float* bc0        = (const float*)d_in[18];
    const float* Wc1        = (const float*)d_in[19];
    const float* bc1        = (const float*)d_in[20];
    const float* Wc2        = (const float*)d_in[21];
    const float* bc2        = (const float*)d_in[22];
    const float* Wr         = (const float*)d_in[23];
    const float* br         = (const float*)d_in[24];
    float* out = (float*)d_out;

    prep_kernel<<<256, 256>>>(Wi0, Wi1, Wi2, Wv0, bv0, Wv1, bv1, Wv2,
                              Wc0, bc0, Wc1, bc1, Wc2, Wr);
    sde_kernel<<<NCTA, NTHR>>>(ts, init_noise, bm, bi0, bi1, bi2,
                               scale_v, bv2, scale_c, bc2, br, out);
}

// round 15
// speedup vs baseline: 1.8808x; 1.8808x over previous
#include <cuda_runtime.h>
#include <cuda_bf16.h>
#include <math.h>

#define BATCH 2048
#define STEPS 64
#define HID   64
#define NZv   32
#define INZ   32
#define DOUT  8
#define BT    14
#define NTHR  512
#define NCTA  ((BATCH + BT - 1) / BT)   /* 147 */

// -------- weight scratch (filled by prep_kernel each call) ----
// mma B-fragments, [ntile][ktile][lane] = {b0h,b1h,b0l,b1l} (bf16 hi/lo split)
__device__ uint4  g_W0Frag [32 * 4 * 32];   // [Wv0|Wc0], K=64 (t col in epilogue)
__device__ uint4  g_W1Frag [32 * 8 * 32];   // [Wv1|Wc1], K=128
__device__ uint4  g_Wv2Frag[ 8 * 8 * 32];   // Wv2, K=128
__device__ uint4  g_WcFrag [256 * 8 * 32];  // Wc2, K=128
__device__ float  g_Wi0T [32  * 128];
__device__ float  g_Wi1T [128 * 128];
__device__ float  g_Wi2T [128 * 64];
__device__ float  g_w0t  [256];             // Wx0[o][0]  (t column)
__device__ float  g_b0   [256];             // [bv0 | bc0]
__device__ float  g_b1   [256];             // [bv1 | bc1]
__device__ float  g_WrT  [64 * 8];          // WrT[h][d]

__device__ __forceinline__ unsigned short bf16_hi_u(float v) {
    return __bfloat16_as_ushort(__float2bfloat16(v));
}
__device__ __forceinline__ unsigned short bf16_lo_u(float v) {
    __nv_bfloat16 h = __float2bfloat16(v);
    return __bfloat16_as_ushort(__float2bfloat16(v - __bfloat162float(h)));
}

__global__ void prep_kernel(const float* __restrict__ Wi0, const float* __restrict__ Wi1,
                            const float* __restrict__ Wi2,
                            const float* __restrict__ Wv0, const float* __restrict__ bv0,
                            const float* __restrict__ Wv1, const float* __restrict__ bv1,
                            const float* __restrict__ Wv2,
                            const float* __restrict__ Wc0, const float* __restrict__ bc0,
                            const float* __restrict__ Wc1, const float* __restrict__ bc1,
                            const float* __restrict__ Wc2, const float* __restrict__ Wr) {
    int tid = blockIdx.x * blockDim.x + threadIdx.x;
    int nt  = gridDim.x * blockDim.x;
    // W0 frags (K=64, source cols shifted by 1 for the t column)
    for (int i = tid; i < 32 * 4 * 32; i += nt) {
        int lane = i & 31, kt = (i >> 5) & 3, ntg = i >> 7;
        int o = ntg * 8 + (lane >> 2);
        int k0 = kt * 16 + 2 * (lane & 3);
        const float* row = (o < 128) ? &Wv0[o * 65] : &Wc0[(o - 128) * 65];
        float w00 = row[k0 + 1], w01 = row[k0 + 2];
        float w10 = row[k0 + 9], w11 = row[k0 + 10];
        uint4 f;
        f.x = (unsigned)bf16_hi_u(w00) | ((unsigned)bf16_hi_u(w01) << 16);
        f.y = (unsigned)bf16_hi_u(w10) | ((unsigned)bf16_hi_u(w11) << 16);
        f.z = (unsigned)bf16_lo_u(w00) | ((unsigned)bf16_lo_u(w01) << 16);
        f.w = (unsigned)bf16_lo_u(w10) | ((unsigned)bf16_lo_u(w11) << 16);
        g_W0Frag[i] = f;
    }
    // W1 frags (K=128)
    for (int i = tid; i < 32 * 8 * 32; i += nt) {
        int lane = i & 31, kt = (i >> 5) & 7, ntg = i >> 8;
        int o = ntg * 8 + (lane >> 2);
        int k0 = kt * 16 + 2 * (lane & 3);
        const float* row = (o < 128) ? &Wv1[o * 128] : &Wc1[(o - 128) * 128];
        float w00 = row[k0], w01 = row[k0 + 1], w10 = row[k0 + 8], w11 = row[k0 + 9];
        uint4 f;
        f.x = (unsigned)bf16_hi_u(w00) | ((unsigned)bf16_hi_u(w01) << 16);
        f.y = (unsigned)bf16_hi_u(w10) | ((unsigned)bf16_hi_u(w11) << 16);
        f.z = (unsigned)bf16_lo_u(w00) | ((unsigned)bf16_lo_u(w01) << 16);
        f.w = (unsigned)bf16_lo_u(w10) | ((unsigned)bf16_lo_u(w11) << 16);
        g_W1Frag[i] = f;
    }
    // Wv2 frags (K=128, N=64)
    for (int i = tid; i < 8 * 8 * 32; i += nt) {
        int lane = i & 31, kt = (i >> 5) & 7, ntg = i >> 8;
        int o = ntg * 8 + (lane >> 2);
        int k0 = kt * 16 + 2 * (lane & 3);
        const float* row = &Wv2[o * 128];
        float w00 = row[k0], w01 = row[k0 + 1], w10 = row[k0 + 8], w11 = row[k0 + 9];
        uint4 f;
        f.x = (unsigned)bf16_hi_u(w00) | ((unsigned)bf16_hi_u(w01) << 16);
        f.y = (unsigned)bf16_hi_u(w10) | ((unsigned)bf16_hi_u(w11) << 16);
        f.z = (unsigned)bf16_lo_u(w00) | ((unsigned)bf16_lo_u(w01) << 16);
        f.w = (unsigned)bf16_lo_u(w10) | ((unsigned)bf16_lo_u(w11) << 16);
        g_Wv2Frag[i] = f;
    }
    // Wc2 frags (K=128, N=2048)
    for (int i = tid; i < 256 * 8 * 32; i += nt) {
        int lane = i & 31, kt = (i >> 5) & 7, ntg = i >> 8;
        int n = ntg * 8 + (lane >> 2);
        int k0 = kt * 16 + 2 * (lane & 3);
        const float* wr = Wc2 + (size_t)n * 128;
        float w00 = wr[k0], w01 = wr[k0 + 1], w10 = wr[k0 + 8], w11 = wr[k0 + 9];
        uint4 f;
        f.x = (unsigned)bf16_hi_u(w00) | ((unsigned)bf16_hi_u(w01) << 16);
        f.y = (unsigned)bf16_hi_u(w10) | ((unsigned)bf16_hi_u(w11) << 16);
        f.z = (unsigned)bf16_lo_u(w00) | ((unsigned)bf16_lo_u(w01) << 16);
        f.w = (unsigned)bf16_lo_u(w10) | ((unsigned)bf16_lo_u(w11) << 16);
        g_WcFrag[i] = f;
    }
    for (int i = tid; i < 32 * 128; i += nt) {
        int k = i >> 7, o = i & 127;
        g_Wi0T[i] = Wi0[o * 32 + k];
    }
    for (int i = tid; i < 128 * 128; i += nt) {
        int k = i >> 7, o = i & 127;
        g_Wi1T[i] = Wi1[o * 128 + k];
    }
    for (int i = tid; i < 128 * 64; i += nt) {
        int k = i >> 6, o = i & 63;
        g_Wi2T[i] = Wi2[o * 128 + k];
    }
    for (int o = tid; o < 256; o += nt) {
        const float* row = (o < 128) ? &Wv0[o * 65] : &Wc0[(o - 128) * 65];
        g_w0t[o] = row[0];
        g_b0[o] = (o < 128) ? bv0[o] : bc0[o - 128];
        g_b1[o] = (o < 128) ? bv1[o] : bc1[o - 128];
    }
    for (int i = tid; i < 64 * 8; i += nt) {
        int h = i >> 3, d = i & 7;
        g_WrT[i] = Wr[d * 64 + h];
    }
}

// fast, accurate-enough transcendentals (abs err ~1e-6)
__device__ __forceinline__ float tanh_fast(float x) {
    float e = __expf(2.0f * x);
    return 1.0f - __fdividef(2.0f, 1.0f + e);
}
__device__ __forceinline__ float lipswish(float x) {
    return 0.909f * __fdividef(x, 1.0f + __expf(-x));
}

#define LDSM4(r0, r1, r2, r3, addr) \
    asm volatile("ldmatrix.sync.aligned.m8n8.x4.shared.b16 {%0,%1,%2,%3}, [%4];" \
        : "=r"(r0), "=r"(r1), "=r"(r2), "=r"(r3) : "r"(addr))

#define MMA_BF16(d, a0, a1, a2, a3, b0, b1) \
    asm volatile("mma.sync.aligned.m16n8k16.row.col.f32.bf16.bf16.f32 " \
        "{%0,%1,%2,%3}, {%4,%5,%6,%7}, {%8,%9}, {%0,%1,%2,%3};" \
        : "+f"(d[0]), "+f"(d[1]), "+f"(d[2]), "+f"(d[3]) \
        : "r"(a0), "r"(a1), "r"(a2), "r"(a3), "r"(b0), "r"(b1))

__global__ void __launch_bounds__(NTHR, 1) sde_kernel(
    const float* __restrict__ ts, const float* __restrict__ init_noise,
    const float* __restrict__ bm,
    const float* __restrict__ bi0, const float* __restrict__ bi1, const float* __restrict__ bi2,
    const float* __restrict__ scale_v, const float* __restrict__ bv2,
    const float* __restrict__ scale_c, const float* __restrict__ bc2,
    const float* __restrict__ br, float* __restrict__ out)
{
    __shared__ float y_s[BT][64];                                             // 3584 B
    __shared__ __align__(16) __nv_bfloat16 yhi_s [16][72],  ylo_s [16][72];   // 4608 B
    __shared__ __align__(16) __nv_bfloat16 h1hi_s[16][264], h1lo_s[16][264];  // 16896 B
    __shared__ __align__(16) __nv_bfloat16 hvhi_s[16][136], hvlo_s[16][136];  // 8704 B
    __shared__ __align__(16) __nv_bfloat16 Ahi_s [16][136], Alo_s [16][136];  // 8704 B
    __shared__ float diff_s[64][15];                                          // 3840 B
    __shared__ float bm_s  [16][33];                                          // 2112 B
    // total 48448 B <= 49152 B

    const int tid  = threadIdx.x;
    const int b0g  = blockIdx.x * BT;
    int nb = BATCH - b0g; if (nb > BT) nb = BT;
    const float ts0 = ts[0];

    const int lane = tid & 31;
    const int wrp  = tid >> 5;                 // 0..15
    const int t    = lane & 3;
    const int g    = lane >> 2;
    const int lrow = lane & 15;
    const int kofs = (lane & 16) ? 8 : 0;
    const unsigned aY   = (unsigned)__cvta_generic_to_shared(&yhi_s [0][0]) + (lrow * 72  + kofs) * 2;
    const unsigned aYl  = (unsigned)__cvta_generic_to_shared(&ylo_s [0][0]) + (lrow * 72  + kofs) * 2;
    const unsigned aH1  = (unsigned)__cvta_generic_to_shared(&h1hi_s[0][0]) + (lrow * 264 + kofs) * 2
                          + ((wrp < 8) ? 0 : 256);   // c-warps contract h1 cols [128,256)
    const unsigned aH1l = (unsigned)__cvta_generic_to_shared(&h1lo_s[0][0]) + (lrow * 264 + kofs) * 2
                          + ((wrp < 8) ? 0 : 256);
    const unsigned aHv  = (unsigned)__cvta_generic_to_shared(&hvhi_s[0][0]) + (lrow * 136 + kofs) * 2;
    const unsigned aHvl = (unsigned)__cvta_generic_to_shared(&hvlo_s[0][0]) + (lrow * 136 + kofs) * 2;
    const unsigned aA   = (unsigned)__cvta_generic_to_shared(&Ahi_s [0][0]) + (lrow * 136 + kofs) * 2;
    const unsigned aAl  = (unsigned)__cvta_generic_to_shared(&Alo_s [0][0]) + (lrow * 136 + kofs) * 2;

    // step-invariant per-thread epilogue constants (registers)
    const int oB0 = wrp * 16 + 2 * t;      // phase B/C q=0 columns
    const int oB1 = oB0 + 8;               // q=1 columns
    const float w0t00 = g_w0t[oB0], w0t01 = g_w0t[oB0 + 1];
    const float w0t10 = g_w0t[oB1], w0t11 = g_w0t[oB1 + 1];
    const float b000 = g_b0[oB0], b001 = g_b0[oB0 + 1];
    const float b010 = g_b0[oB1], b011 = g_b0[oB1 + 1];
    const float b100 = g_b1[oB0], b101 = g_b1[oB0 + 1];
    const float b110 = g_b1[oB1], b111 = g_b1[oB1 + 1];
    const int oD = (wrp & 7) * 8 + 2 * t;   // phase D columns (warps 0..7)
    const float bv20 = bv2[oD], bv21 = bv2[oD + 1];
    const float sv0  = scale_v[oD], sv1 = scale_v[oD + 1];

    // ---------------- initial MLP: init_noise -> y0 ----------------
    {
        float* nbuf = (float*)diff_s;   // [16][32] staging (2048 B <= 3840 B)
        for (int i = tid; i < 16 * 32; i += NTHR) {
            int b = i >> 5, z = i & 31;
            nbuf[i] = (b < nb) ? init_noise[(size_t)(b0g + b) * INZ + z] : 0.0f;
        }
        __syncthreads();
        {   // L0: 32 -> 128, relu -> h1 hi/lo (cols 0..127)
            int o = tid & 127, gg = tid >> 7;
            float acc[4];
            float bias = bi0[o];
            #pragma unroll
            for (int j = 0; j < 4; j++) acc[j] = bias;
            for (int k = 0; k < 32; k++) {
                float w = g_Wi0T[k * 128 + o];
                #pragma unroll
                for (int j = 0; j < 4; j++) acc[j] = fmaf(w, nbuf[(gg * 4 + j) * 32 + k], acc[j]);
            }
            #pragma unroll
            for (int j = 0; j < 4; j++) {
                float v = fmaxf(acc[j], 0.0f);
                __nv_bfloat16 h = __float2bfloat16(v);
                h1hi_s[gg * 4 + j][o] = h;
                h1lo_s[gg * 4 + j][o] = __float2bfloat16(v - __bfloat162float(h));
            }
        }
        __syncthreads();
        {   // L1: 128 -> 128, relu -> hv hi/lo
            int o = tid & 127, gg = tid >> 7;
            float acc[4];
            float bias = bi1[o];
            #pragma unroll
            for (int j = 0; j < 4; j++) acc[j] = bias;
            for (int k = 0; k < 128; k++) {
                float w = g_Wi1T[k * 128 + o];
                #pragma unroll
                for (int j = 0; j < 4; j++) {
                    float a = __bfloat162float(h1hi_s[gg * 4 + j][k]) +
                              __bfloat162float(h1lo_s[gg * 4 + j][k]);
                    acc[j] = fmaf(w, a, acc[j]);
                }
            }
            #pragma unroll
            for (int j = 0; j < 4; j++) {
                float v = fmaxf(acc[j], 0.0f);
                __nv_bfloat16 h = __float2bfloat16(v);
                hvhi_s[gg * 4 + j][o] = h;
                hvlo_s[gg * 4 + j][o] = __float2bfloat16(v - __bfloat162float(h));
            }
        }
        __syncthreads();
        {   // L2: 128 -> 64, identity -> y0 (fp32 + hi/lo; pad rows 14,15 zeroed)
            int o = tid & 63, gg = tid >> 6;
            float bias = bi2[o];
            float a0 = bias, a1 = bias;
            for (int k = 0; k < 128; k++) {
                float w = g_Wi2T[k * 64 + o];
                float x0 = __bfloat162float(hvhi_s[gg * 2 + 0][k]) + __bfloat162float(hvlo_s[gg * 2 + 0][k]);
                float x1 = __bfloat162float(hvhi_s[gg * 2 + 1][k]) + __bfloat162float(hvlo_s[gg * 2 + 1][k]);
                a0 = fmaf(w, x0, a0);
                a1 = fmaf(w, x1, a1);
            }
            #pragma unroll
            for (int jj = 0; jj < 2; jj++) {
                int b = gg * 2 + jj;
                float v = jj ? a1 : a0;
                if (b < BT) {
                    y_s[b][o] = v;
                    __nv_bfloat16 h = __float2bfloat16(v);
                    yhi_s[b][o] = h;
                    ylo_s[b][o] = __float2bfloat16(v - __bfloat162float(h));
                } else {
                    yhi_s[b][o] = __float2bfloat16(0.0f);
                    ylo_s[b][o] = __float2bfloat16(0.0f);
                }
            }
        }
        __syncthreads();
    }

    // ---------------- time scan ----------------
    for (int step = 0; step < STEPS; step++) {
        // stage noise (nb-guarded: last CTA must not read bm out of bounds)
        if (tid < BT * 32) {
            int b = tid >> 5, z = tid & 31;
            bm_s[b][z] = (b < nb)
                ? bm[(size_t)(b0g + b) * (STEPS * NZv) + step * NZv + z] : 0.0f;
        }
        const float tcur = ts0 + (float)step;
        // ---- phase B: layer0 (256 outputs, K=64 mma; t/bias in epilogue) ----
        {
            float acc[2][4];
            #pragma unroll
            for (int q = 0; q < 2; q++)
                #pragma unroll
                for (int r = 0; r < 4; r++) acc[q][r] = 0.0f;
            #pragma unroll
            for (int kt = 0; kt < 4; kt++) {
                unsigned ah0, ah1, ah2, ah3, al0, al1, al2, al3;
                LDSM4(ah0, ah1, ah2, ah3, aY  + kt * 32);
                LDSM4(al0, al1, al2, al3, aYl + kt * 32);
                #pragma unroll
                for (int q = 0; q < 2; q++) {
                    uint4 W = __ldg(&g_W0Frag[(((wrp * 2 + q) * 4) + kt) * 32 + lane]);
                    MMA_BF16(acc[q], ah0, ah1, ah2, ah3, W.x, W.y);
                    MMA_BF16(acc[q], ah0, ah1, ah2, ah3, W.z, W.w);
                    MMA_BF16(acc[q], al0, al1, al2, al3, W.x, W.y);
                }
            }
            #pragma unroll
            for (int q = 0; q < 2; q++) {
                int o0 = (q == 0) ? oB0 : oB1;
                float bia0 = fmaf((q == 0) ? w0t00 : w0t10, tcur, (q == 0) ? b000 : b010);
                float bia1 = fmaf((q == 0) ? w0t01 : w0t11, tcur, (q == 0) ? b001 : b011);
                float v00 = lipswish(acc[q][0] + bia0);
                float v01 = lipswish(acc[q][1] + bia1);
                float v10 = lipswish(acc[q][2] + bia0);
                float v11 = lipswish(acc[q][3] + bia1);
                __nv_bfloat16 h00 = __float2bfloat16(v00), h01 = __float2bfloat16(v01);
                __nv_bfloat16 h10 = __float2bfloat16(v10), h11 = __float2bfloat16(v11);
                h1hi_s[g][o0] = h00;          h1lo_s[g][o0] = __float2bfloat16(v00 - __bfloat162float(h00));
                h1hi_s[g][o0 + 1] = h01;      h1lo_s[g][o0 + 1] = __float2bfloat16(v01 - __bfloat162float(h01));
                h1hi_s[g + 8][o0] = h10;      h1lo_s[g + 8][o0] = __float2bfloat16(v10 - __bfloat162float(h10));
                h1hi_s[g + 8][o0 + 1] = h11;  h1lo_s[g + 8][o0 + 1] = __float2bfloat16(v11 - __bfloat162float(h11));
            }
        }
        __syncthreads();
        // ---- phase C: layer1 (256 outputs, K=128 mma) ----
        {
            float acc[2][4];
            #pragma unroll
            for (int q = 0; q < 2; q++)
                #pragma unroll
                for (int r = 0; r < 4; r++) acc[q][r] = 0.0f;
            #pragma unroll
            for (int kt = 0; kt < 8; kt++) {
                unsigned ah0, ah1, ah2, ah3, al0, al1, al2, al3;
                LDSM4(ah0, ah1, ah2, ah3, aH1  + kt * 32);
                LDSM4(al0, al1, al2, al3, aH1l + kt * 32);
                #pragma unroll
                for (int q = 0; q < 2; q++) {
                    uint4 W = __ldg(&g_W1Frag[(((wrp * 2 + q) * 8) + kt) * 32 + lane]);
                    MMA_BF16(acc[q], ah0, ah1, ah2, ah3, W.x, W.y);
                    MMA_BF16(acc[q], ah0, ah1, ah2, ah3, W.z, W.w);
                    MMA_BF16(acc[q], al0, al1, al2, al3, W.x, W.y);
                }
            }
            #pragma unroll
            for (int q = 0; q < 2; q++) {
                int o0 = (q == 0) ? oB0 : oB1, o1 = o0 + 1;
                float v00 = lipswish(acc[q][0] + ((q == 0) ? b100 : b110));
                float v01 = lipswish(acc[q][1] + ((q == 0) ? b101 : b111));
                float v10 = lipswish(acc[q][2] + ((q == 0) ? b100 : b110));
                float v11 = lipswish(acc[q][3] + ((q == 0) ? b101 : b111));
                __nv_bfloat16 h00 = __float2bfloat16(v00), h01 = __float2bfloat16(v01);
                __nv_bfloat16 h10 = __float2bfloat16(v10), h11 = __float2bfloat16(v11);
                if (wrp < 8) {
                    hvhi_s[g][o0] = h00;      hvlo_s[g][o0] = __float2bfloat16(v00 - __bfloat162float(h00));
                    hvhi_s[g][o1] = h01;      hvlo_s[g][o1] = __float2bfloat16(v01 - __bfloat162float(h01));
                    hvhi_s[g + 8][o0] = h10;  hvlo_s[g + 8][o0] = __float2bfloat16(v10 - __bfloat162float(h10));
                    hvhi_s[g + 8][o1] = h11;  hvlo_s[g + 8][o1] = __float2bfloat16(v11 - __bfloat162float(h11));
                } else {
                    int k0 = o0 - 128, k1 = o1 - 128;
                    Ahi_s[g][k0] = h00;       Alo_s[g][k0] = __float2bfloat16(v00 - __bfloat162float(h00));
                    Ahi_s[g][k1] = h01;       Alo_s[g][k1] = __float2bfloat16(v01 - __bfloat162float(h01));
                    Ahi_s[g + 8][k0] = h10;   Alo_s[g + 8][k0] = __float2bfloat16(v10 - __bfloat162float(h10));
                    Ahi_s[g + 8][k1] = h11;   Alo_s[g + 8][k1] = __float2bfloat16(v11 - __bfloat162float(h11));
                }
            }
        }
        __syncthreads();
        // ---- phase D: drift head (64 outputs, K=128 mma), warps 0..7; y in place ----
        if (wrp < 8) {
            float acc[4] = {0.0f, 0.0f, 0.0f, 0.0f};
            #pragma unroll
            for (int kt = 0; kt < 8; kt++) {
                unsigned ah0, ah1, ah2, ah3, al0, al1, al2, al3;
                LDSM4(ah0, ah1, ah2, ah3, aHv  + kt * 32);
                LDSM4(al0, al1, al2, al3, aHvl + kt * 32);
                uint4 W = __ldg(&g_Wv2Frag[(wrp * 8 + kt) * 32 + lane]);
                MMA_BF16(acc, ah0, ah1, ah2, ah3, W.x, W.y);
                MMA_BF16(acc, ah0, ah1, ah2, ah3, W.z, W.w);
                MMA_BF16(acc, al0, al1, al2, al3, W.x, W.y);
            }
            if (g < BT) {
                y_s[g][oD]     += sv0 * tanh_fast(acc[0] + bv20);
                y_s[g][oD + 1] += sv1 * tanh_fast(acc[1] + bv21);
            }
            if (g + 8 < BT) {
                y_s[g + 8][oD]     += sv0 * tanh_fast(acc[2] + bv20);
                y_s[g + 8][oD + 1] += sv1 * tanh_fast(acc[3] + bv21);
            }
        }
        // ---- phase E: controlled field mma, 4 single-h passes with 2-deep
        //      register-pipelined weight prefetch (hides 234-262 cyc L2 latency) ----
        #pragma unroll 1
        for (int p = 0; p < 4; p++) {
            const int h = wrp * 4 + p;
            const uint4* wbase = g_WcFrag + ((size_t)h * 4 * 8) * 32 + lane;  // q stride 256, kt stride 32
            uint4 Wbuf[3][4];
            #pragma unroll
            for (int q = 0; q < 4; q++) Wbuf[0][q] = __ldcg(wbase + q * 256);
            #pragma unroll
            for (int q = 0; q < 4; q++) Wbuf[1][q] = __ldcg(wbase + q * 256 + 32);
            float acc[4][4];
            #pragma unroll
            for (int q = 0; q < 4; q++)
                #pragma unroll
                for (int r = 0; r < 4; r++) acc[q][r] = 0.0f;
            #pragma unroll
            for (int kt = 0; kt < 8; kt++) {
                if (kt < 6) {
                    #pragma unroll
                    for (int q = 0; q < 4; q++)
                        Wbuf[(kt + 2) % 3][q] = __ldcg(wbase + q * 256 + (kt + 2) * 32);
                }
                unsigned ah0, ah1, ah2, ah3, al0, al1, al2, al3;
                LDSM4(ah0, ah1, ah2, ah3, aA  + kt * 32);
                LDSM4(al0, al1, al2, al3, aAl + kt * 32);
                #pragma unroll
                for (int q = 0; q < 4; q++) {
                    uint4 W = Wbuf[kt % 3][q];
                    MMA_BF16(acc[q], ah0, ah1, ah2, ah3, W.x, W.y);
                    MMA_BF16(acc[q], ah0, ah1, ah2, ah3, W.z, W.w);
                    MMA_BF16(acc[q], al0, al1, al2, al3, W.x, W.y);
                }
            }
            // epilogue: bias + tanh + scale + noise (same math/order as R12)
            float s0 = 0.0f, s1 = 0.0f;
            #pragma unroll
            for (int q = 0; q < 4; q++) {
                int n0 = (h * 4 + q) * 8 + 2 * t;
                float2 sc = __ldg((const float2*)&scale_c[n0]);
                float2 bc = __ldg((const float2*)&bc2[n0]);
                int nz0 = n0 & 31;
                float t0 = sc.x * tanh_fast(acc[q][0] + bc.x);
                float t1 = sc.y * tanh_fast(acc[q][1] + bc.y);
                float t2 = sc.x * tanh_fast(acc[q][2] + bc.x);
                float t3 = sc.y * tanh_fast(acc[q][3] + bc.y);
                s0 = fmaf(t0, bm_s[g][nz0],     fmaf(t1, bm_s[g][nz0 + 1],     s0));
                s1 = fmaf(t2, bm_s[g + 8][nz0], fmaf(t3, bm_s[g + 8][nz0 + 1], s1));
            }
            s0 += __shfl_xor_sync(0xffffffffu, s0, 1);
            s0 += __shfl_xor_sync(0xffffffffu, s0, 2);
            s1 += __shfl_xor_sync(0xffffffffu, s1, 1);
            s1 += __shfl_xor_sync(0xffffffffu, s1, 2);
            if (t == 0) {
                diff_s[h][g] = s0;
                if (g < 6) diff_s[h][g + 8] = s1;
            }
        }
        __syncthreads();
        // ---- phase F: y += diff — FIXED: strided loop, BT*64 = 896 > NTHR = 512 ----
        for (int i = tid; i < BT * 64; i += NTHR) {
            int b = i >> 6, h = i & 63;
            float v = y_s[b][h] + diff_s[h][b];
            y_s[b][h] = v;
            __nv_bfloat16 hh = __float2bfloat16(v);
            yhi_s[b][h] = hh;
            ylo_s[b][h] = __float2bfloat16(v - __bfloat162float(hh));
        }
        __syncthreads();
        // ---- readout: out[b, step, :] = y @ Wr^T + br ----
        if (tid < BT * DOUT) {
            int b = tid >> 3, d = tid & 7;
            if (b < nb) {
                float acc = br[d];
                #pragma unroll 8
                for (int h = 0; h < 64; h++)
                    acc = fmaf(y_s[b][h], g_WrT[h * 8 + d], acc);
                out[(size_t)(b0g + b) * (STEPS * DOUT) + step * DOUT + d] = acc;
            }
        }
    }
}

extern "C" void kernel_launch(void* const* d_in, const int* in_sizes, int n_in,
                              void* d_out, int out_size) {
    (void)in_sizes; (void)n_in; (void)out_size;
    const float* ts         = (const float*)d_in[0];
    const float* init_noise = (const float*)d_in[1];
    const float* bm         = (const float*)d_in[2];
    const float* Wi0        = (const float*)d_in[3];
    const float* bi0        = (const float*)d_in[4];
    const float* Wi1        = (const float*)d_in[5];
    const float* bi1        = (const float*)d_in[6];
    const float* Wi2        = (const float*)d_in[7];
    const float* bi2        = (const float*)d_in[8];
    const float* scale_v    = (const float*)d_in[9];
    const float* Wv0        = (const float*)d_in[10];
    const float* bv0        = (const float*)d_in[11];
    const float* Wv1        = (const float*)d_in[12];
    const float* bv1        = (const float*)d_in[13];
    const float* Wv2        = (const float*)d_in[14];
    const float* bv2        = (const float*)d_in[15];
    const float* scale_c    = (const float*)d_in[16];
    const float* Wc0        = (const float*)d_in[17];
    const float* bc0        = (const float*)d_in[18];
    const float* Wc1        = (const float*)d_in[19];
    const float* bc1        = (const float*)d_in[20];
    const float* Wc2        = (const float*)d_in[21];
    const float* bc2        = (const float*)d_in[22];
    const float* Wr         = (const float*)d_in[23];
    const float* br         = (const float*)d_in[24];
    float* out = (float*)d_out;

    prep_kernel<<<256, 256>>>(Wi0, Wi1, Wi2, Wv0, bv0, Wv1, bv1, Wv2,
                              Wc0, bc0, Wc1, bc1, Wc2, Wr);
    sde_kernel<<<NCTA, NTHR>>>(ts, init_noise, bm, bi0, bi1, bi2,
                               scale_v, bv2, scale_c, bc2, br, out);
}

// round 16
// speedup vs baseline: 1.9504x; 1.0370x over previous
#include <cuda_runtime.h>
#include <cuda_bf16.h>
#include <math.h>

#define BATCH 2048
#define STEPS 64
#define HID   64
#define NZv   32
#define INZ   32
#define DOUT  8
#define BT    14
#define NTHR  512
#define NCTA  ((BATCH + BT - 1) / BT)   /* 147 */

// -------- weight scratch (filled by prep_kernel each call) ----
// mma B-fragments, [ntile][ktile][lane] = {b0h,b1h,b0l,b1l} (bf16 hi/lo split)
__device__ uint4  g_W0Frag [32 * 4 * 32];   // [Wv0|Wc0], K=64 (t col in epilogue)
__device__ uint4  g_W1Frag [32 * 8 * 32];   // [Wv1|Wc1], K=128
__device__ uint4  g_Wv2Frag[ 8 * 8 * 32];   // Wv2, K=128
__device__ uint4  g_WcFrag [256 * 8 * 32];  // Wc2, K=128
__device__ float  g_Wi0T [32  * 128];
__device__ float  g_Wi1T [128 * 128];
__device__ float  g_Wi2T [128 * 64];
__device__ float  g_w0t  [256];             // Wx0[o][0]  (t column)
__device__ float  g_b0   [256];             // [bv0 | bc0]
__device__ float  g_b1   [256];             // [bv1 | bc1]
__device__ float  g_WrT  [64 * 8];          // WrT[h][d]

__device__ __forceinline__ unsigned short bf16_hi_u(float v) {
    return __bfloat16_as_ushort(__float2bfloat16(v));
}
__device__ __forceinline__ unsigned short bf16_lo_u(float v) {
    __nv_bfloat16 h = __float2bfloat16(v);
    return __bfloat16_as_ushort(__float2bfloat16(v - __bfloat162float(h)));
}

__global__ void prep_kernel(const float* __restrict__ Wi0, const float* __restrict__ Wi1,
                            const float* __restrict__ Wi2,
                            const float* __restrict__ Wv0, const float* __restrict__ bv0,
                            const float* __restrict__ Wv1, const float* __restrict__ bv1,
                            const float* __restrict__ Wv2,
                            const float* __restrict__ Wc0, const float* __restrict__ bc0,
                            const float* __restrict__ Wc1, const float* __restrict__ bc1,
                            const float* __restrict__ Wc2, const float* __restrict__ Wr) {
    int tid = blockIdx.x * blockDim.x + threadIdx.x;
    int nt  = gridDim.x * blockDim.x;
    // W0 frags (K=64, source cols shifted by 1 for the t column)
    for (int i = tid; i < 32 * 4 * 32; i += nt) {
        int lane = i & 31, kt = (i >> 5) & 3, ntg = i >> 7;
        int o = ntg * 8 + (lane >> 2);
        int k0 = kt * 16 + 2 * (lane & 3);
        const float* row = (o < 128) ? &Wv0[o * 65] : &Wc0[(o - 128) * 65];
        float w00 = row[k0 + 1], w01 = row[k0 + 2];
        float w10 = row[k0 + 9], w11 = row[k0 + 10];
        uint4 f;
        f.x = (unsigned)bf16_hi_u(w00) | ((unsigned)bf16_hi_u(w01) << 16);
        f.y = (unsigned)bf16_hi_u(w10) | ((unsigned)bf16_hi_u(w11) << 16);
        f.z = (unsigned)bf16_lo_u(w00) | ((unsigned)bf16_lo_u(w01) << 16);
        f.w = (unsigned)bf16_lo_u(w10) | ((unsigned)bf16_lo_u(w11) << 16);
        g_W0Frag[i] = f;
    }
    // W1 frags (K=128)
    for (int i = tid; i < 32 * 8 * 32; i += nt) {
        int lane = i & 31, kt = (i >> 5) & 7, ntg = i >> 8;
        int o = ntg * 8 + (lane >> 2);
        int k0 = kt * 16 + 2 * (lane & 3);
        const float* row = (o < 128) ? &Wv1[o * 128] : &Wc1[(o - 128) * 128];
        float w00 = row[k0], w01 = row[k0 + 1], w10 = row[k0 + 8], w11 = row[k0 + 9];
        uint4 f;
        f.x = (unsigned)bf16_hi_u(w00) | ((unsigned)bf16_hi_u(w01) << 16);
        f.y = (unsigned)bf16_hi_u(w10) | ((unsigned)bf16_hi_u(w11) << 16);
        f.z = (unsigned)bf16_lo_u(w00) | ((unsigned)bf16_lo_u(w01) << 16);
        f.w = (unsigned)bf16_lo_u(w10) | ((unsigned)bf16_lo_u(w11) << 16);
        g_W1Frag[i] = f;
    }
    // Wv2 frags (K=128, N=64)
    for (int i = tid; i < 8 * 8 * 32; i += nt) {
        int lane = i & 31, kt = (i >> 5) & 7, ntg = i >> 8;
        int o = ntg * 8 + (lane >> 2);
        int k0 = kt * 16 + 2 * (lane & 3);
        const float* row = &Wv2[o * 128];
        float w00 = row[k0], w01 = row[k0 + 1], w10 = row[k0 + 8], w11 = row[k0 + 9];
        uint4 f;
        f.x = (unsigned)bf16_hi_u(w00) | ((unsigned)bf16_hi_u(w01) << 16);
        f.y = (unsigned)bf16_hi_u(w10) | ((unsigned)bf16_hi_u(w11) << 16);
        f.z = (unsigned)bf16_lo_u(w00) | ((unsigned)bf16_lo_u(w01) << 16);
        f.w = (unsigned)bf16_lo_u(w10) | ((unsigned)bf16_lo_u(w11) << 16);
        g_Wv2Frag[i] = f;
    }
    // Wc2 frags (K=128, N=2048)
    for (int i = tid; i < 256 * 8 * 32; i += nt) {
        int lane = i & 31, kt = (i >> 5) & 7, ntg = i >> 8;
        int n = ntg * 8 + (lane >> 2);
        int k0 = kt * 16 + 2 * (lane & 3);
        const float* wr = Wc2 + (size_t)n * 128;
        float w00 = wr[k0], w01 = wr[k0 + 1], w10 = wr[k0 + 8], w11 = wr[k0 + 9];
        uint4 f;
        f.x = (unsigned)bf16_hi_u(w00) | ((unsigned)bf16_hi_u(w01) << 16);
        f.y = (unsigned)bf16_hi_u(w10) | ((unsigned)bf16_hi_u(w11) << 16);
        f.z = (unsigned)bf16_lo_u(w00) | ((unsigned)bf16_lo_u(w01) << 16);
        f.w = (unsigned)bf16_lo_u(w10) | ((unsigned)bf16_lo_u(w11) << 16);
        g_WcFrag[i] = f;
    }
    for (int i = tid; i < 32 * 128; i += nt) {
        int k = i >> 7, o = i & 127;
        g_Wi0T[i] = Wi0[o * 32 + k];
    }
    for (int i = tid; i < 128 * 128; i += nt) {
        int k = i >> 7, o = i & 127;
        g_Wi1T[i] = Wi1[o * 128 + k];
    }
    for (int i = tid; i < 128 * 64; i += nt) {
        int k = i >> 6, o = i & 63;
        g_Wi2T[i] = Wi2[o * 128 + k];
    }
    for (int o = tid; o < 256; o += nt) {
        const float* row = (o < 128) ? &Wv0[o * 65] : &Wc0[(o - 128) * 65];
        g_w0t[o] = row[0];
        g_b0[o] = (o < 128) ? bv0[o] : bc0[o - 128];
        g_b1[o] = (o < 128) ? bv1[o] : bc1[o - 128];
    }
    for (int i = tid; i < 64 * 8; i += nt) {
        int h = i >> 3, d = i & 7;
        g_WrT[i] = Wr[d * 64 + h];
    }
}

// fast, accurate-enough transcendentals (abs err ~1e-6)
__device__ __forceinline__ float tanh_fast(float x) {
    float e = __expf(2.0f * x);
    return 1.0f - __fdividef(2.0f, 1.0f + e);
}
__device__ __forceinline__ float lipswish(float x) {
    return 0.909f * __fdividef(x, 1.0f + __expf(-x));
}

#define LDSM4(r0, r1, r2, r3, addr) \
    asm volatile("ldmatrix.sync.aligned.m8n8.x4.shared.b16 {%0,%1,%2,%3}, [%4];" \
        : "=r"(r0), "=r"(r1), "=r"(r2), "=r"(r3) : "r"(addr))

// NOTE: no `volatile` — pure register op, lets nvcc/ptxas interleave
// independent HMMA chains (asm volatile serialized dependent MMAs and
// held the tensor pipe at 51%).
#define MMA_BF16(d, a0, a1, a2, a3, b0, b1) \
    asm("mma.sync.aligned.m16n8k16.row.col.f32.bf16.bf16.f32 " \
        "{%0,%1,%2,%3}, {%4,%5,%6,%7}, {%8,%9}, {%0,%1,%2,%3};" \
        : "+f"(d[0]), "+f"(d[1]), "+f"(d[2]), "+f"(d[3]) \
        : "r"(a0), "r"(a1), "r"(a2), "r"(a3), "r"(b0), "r"(b1))

__global__ void __launch_bounds__(NTHR, 1) sde_kernel(
    const float* __restrict__ ts, const float* __restrict__ init_noise,
    const float* __restrict__ bm,
    const float* __restrict__ bi0, const float* __restrict__ bi1, const float* __restrict__ bi2,
    const float* __restrict__ scale_v, const float* __restrict__ bv2,
    const float* __restrict__ scale_c, const float* __restrict__ bc2,
    const float* __restrict__ br, float* __restrict__ out)
{
    __shared__ float y_s[BT][64];                                             // 3584 B
    __shared__ __align__(16) __nv_bfloat16 yhi_s [16][72],  ylo_s [16][72];   // 4608 B
    __shared__ __align__(16) __nv_bfloat16 h1hi_s[16][264], h1lo_s[16][264];  // 16896 B
    __shared__ __align__(16) __nv_bfloat16 hvhi_s[16][136], hvlo_s[16][136];  // 8704 B
    __shared__ __align__(16) __nv_bfloat16 Ahi_s [16][136], Alo_s [16][136];  // 8704 B
    __shared__ float diff_s[64][15];                                          // 3840 B
    __shared__ float bm_s  [16][33];                                          // 2112 B
    // total 48448 B <= 49152 B

    const int tid  = threadIdx.x;
    const int b0g  = blockIdx.x * BT;
    int nb = BATCH - b0g; if (nb > BT) nb = BT;
    const float ts0 = ts[0];

    const int lane = tid & 31;
    const int wrp  = tid >> 5;                 // 0..15
    const int t    = lane & 3;
    const int g    = lane >> 2;
    const int lrow = lane & 15;
    const int kofs = (lane & 16) ? 8 : 0;
    const unsigned aY   = (unsigned)__cvta_generic_to_shared(&yhi_s [0][0]) + (lrow * 72  + kofs) * 2;
    const unsigned aYl  = (unsigned)__cvta_generic_to_shared(&ylo_s [0][0]) + (lrow * 72  + kofs) * 2;
    const unsigned aH1  = (unsigned)__cvta_generic_to_shared(&h1hi_s[0][0]) + (lrow * 264 + kofs) * 2
                          + ((wrp < 8) ? 0 : 256);   // c-warps contract h1 cols [128,256)
    const unsigned aH1l = (unsigned)__cvta_generic_to_shared(&h1lo_s[0][0]) + (lrow * 264 + kofs) * 2
                          + ((wrp < 8) ? 0 : 256);
    const unsigned aHv  = (unsigned)__cvta_generic_to_shared(&hvhi_s[0][0]) + (lrow * 136 + kofs) * 2;
    const unsigned aHvl = (unsigned)__cvta_generic_to_shared(&hvlo_s[0][0]) + (lrow * 136 + kofs) * 2;
    const unsigned aA   = (unsigned)__cvta_generic_to_shared(&Ahi_s [0][0]) + (lrow * 136 + kofs) * 2;
    const unsigned aAl  = (unsigned)__cvta_generic_to_shared(&Alo_s [0][0]) + (lrow * 136 + kofs) * 2;

    // step-invariant per-thread epilogue constants (registers)
    const int oB0 = wrp * 16 + 2 * t;      // phase B/C q=0 columns
    const int oB1 = oB0 + 8;               // q=1 columns
    const float w0t00 = g_w0t[oB0], w0t01 = g_w0t[oB0 + 1];
    const float w0t10 = g_w0t[oB1], w0t11 = g_w0t[oB1 + 1];
    const float b000 = g_b0[oB0], b001 = g_b0[oB0 + 1];
    const float b010 = g_b0[oB1], b011 = g_b0[oB1 + 1];
    const float b100 = g_b1[oB0], b101 = g_b1[oB0 + 1];
    const float b110 = g_b1[oB1], b111 = g_b1[oB1 + 1];
    const int oD = (wrp & 7) * 8 + 2 * t;   // phase D columns (warps 0..7)
    const float bv20 = bv2[oD], bv21 = bv2[oD + 1];
    const float sv0  = scale_v[oD], sv1 = scale_v[oD + 1];

    // ---------------- initial MLP: init_noise -> y0 ----------------
    {
        float* nbuf = (float*)diff_s;   // [16][32] staging (2048 B <= 3840 B)
        for (int i = tid; i < 16 * 32; i += NTHR) {
            int b = i >> 5, z = i & 31;
            nbuf[i] = (b < nb) ? init_noise[(size_t)(b0g + b) * INZ + z] : 0.0f;
        }
        __syncthreads();
        {   // L0: 32 -> 128, relu -> h1 hi/lo (cols 0..127)
            int o = tid & 127, gg = tid >> 7;
            float acc[4];
            float bias = bi0[o];
            #pragma unroll
            for (int j = 0; j < 4; j++) acc[j] = bias;
            for (int k = 0; k < 32; k++) {
                float w = g_Wi0T[k * 128 + o];
                #pragma unroll
                for (int j = 0; j < 4; j++) acc[j] = fmaf(w, nbuf[(gg * 4 + j) * 32 + k], acc[j]);
            }
            #pragma unroll
            for (int j = 0; j < 4; j++) {
                float v = fmaxf(acc[j], 0.0f);
                __nv_bfloat16 h = __float2bfloat16(v);
                h1hi_s[gg * 4 + j][o] = h;
                h1lo_s[gg * 4 + j][o] = __float2bfloat16(v - __bfloat162float(h));
            }
        }
        __syncthreads();
        {   // L1: 128 -> 128, relu -> hv hi/lo
            int o = tid & 127, gg = tid >> 7;
            float acc[4];
            float bias = bi1[o];
            #pragma unroll
            for (int j = 0; j < 4; j++) acc[j] = bias;
            for (int k = 0; k < 128; k++) {
                float w = g_Wi1T[k * 128 + o];
                #pragma unroll
                for (int j = 0; j < 4; j++) {
                    float a = __bfloat162float(h1hi_s[gg * 4 + j][k]) +
                              __bfloat162float(h1lo_s[gg * 4 + j][k]);
                    acc[j] = fmaf(w, a, acc[j]);
                }
            }
            #pragma unroll
            for (int j = 0; j < 4; j++) {
                float v = fmaxf(acc[j], 0.0f);
                __nv_bfloat16 h = __float2bfloat16(v);
                hvhi_s[gg * 4 + j][o] = h;
                hvlo_s[gg * 4 + j][o] = __float2bfloat16(v - __bfloat162float(h));
            }
        }
        __syncthreads();
        {   // L2: 128 -> 64, identity -> y0 (fp32 + hi/lo; pad rows 14,15 zeroed)
            int o = tid & 63, gg = tid >> 6;
            float bias = bi2[o];
            float a0 = bias, a1 = bias;
            for (int k = 0; k < 128; k++) {
                float w = g_Wi2T[k * 64 + o];
                float x0 = __bfloat162float(hvhi_s[gg * 2 + 0][k]) + __bfloat162float(hvlo_s[gg * 2 + 0][k]);
                float x1 = __bfloat162float(hvhi_s[gg * 2 + 1][k]) + __bfloat162float(hvlo_s[gg * 2 + 1][k]);
                a0 = fmaf(w, x0, a0);
                a1 = fmaf(w, x1, a1);
            }
            #pragma unroll
            for (int jj = 0; jj < 2; jj++) {
                int b = gg * 2 + jj;
                float v = jj ? a1 : a0;
                if (b < BT) {
                    y_s[b][o] = v;
                    __nv_bfloat16 h = __float2bfloat16(v);
                    yhi_s[b][o] = h;
                    ylo_s[b][o] = __float2bfloat16(v - __bfloat162float(h));
                } else {
                    yhi_s[b][o] = __float2bfloat16(0.0f);
                    ylo_s[b][o] = __float2bfloat16(0.0f);
                }
            }
        }
        __syncthreads();
    }

    // ---------------- time scan ----------------
    for (int step = 0; step < STEPS; step++) {
        // stage noise (nb-guarded)
        if (tid < BT * 32) {
            int b = tid >> 5, z = tid & 31;
            bm_s[b][z] = (b < nb)
                ? bm[(size_t)(b0g + b) * (STEPS * NZv) + step * NZv + z] : 0.0f;
        }
        const float tcur = ts0 + (float)step;
        // ---- phase B: layer0 (256 outputs, K=64 mma; t/bias in epilogue) ----
        {
            float acc[2][4];
            #pragma unroll
            for (int q = 0; q < 2; q++)
                #pragma unroll
                for (int r = 0; r < 4; r++) acc[q][r] = 0.0f;
            #pragma unroll
            for (int kt = 0; kt < 4; kt++) {
                unsigned ah0, ah1, ah2, ah3, al0, al1, al2, al3;
                LDSM4(ah0, ah1, ah2, ah3, aY  + kt * 32);
                LDSM4(al0, al1, al2, al3, aYl + kt * 32);
                uint4 W0q = __ldg(&g_W0Frag[((wrp * 2 + 0) * 4 + kt) * 32 + lane]);
                uint4 W1q = __ldg(&g_W0Frag[((wrp * 2 + 1) * 4 + kt) * 32 + lane]);
                // term-interleaved issue order
                MMA_BF16(acc[0], ah0, ah1, ah2, ah3, W0q.x, W0q.y);
                MMA_BF16(acc[1], ah0, ah1, ah2, ah3, W1q.x, W1q.y);
                MMA_BF16(acc[0], ah0, ah1, ah2, ah3, W0q.z, W0q.w);
                MMA_BF16(acc[1], ah0, ah1, ah2, ah3, W1q.z, W1q.w);
                MMA_BF16(acc[0], al0, al1, al2, al3, W0q.x, W0q.y);
                MMA_BF16(acc[1], al0, al1, al2, al3, W1q.x, W1q.y);
            }
            #pragma unroll
            for (int q = 0; q < 2; q++) {
                int o0 = (q == 0) ? oB0 : oB1;
                float bia0 = fmaf((q == 0) ? w0t00 : w0t10, tcur, (q == 0) ? b000 : b010);
                float bia1 = fmaf((q == 0) ? w0t01 : w0t11, tcur, (q == 0) ? b001 : b011);
                float v00 = lipswish(acc[q][0] + bia0);
                float v01 = lipswish(acc[q][1] + bia1);
                float v10 = lipswish(acc[q][2] + bia0);
                float v11 = lipswish(acc[q][3] + bia1);
                __nv_bfloat16 h00 = __float2bfloat16(v00), h01 = __float2bfloat16(v01);
                __nv_bfloat16 h10 = __float2bfloat16(v10), h11 = __float2bfloat16(v11);
                h1hi_s[g][o0] = h00;          h1lo_s[g][o0] = __float2bfloat16(v00 - __bfloat162float(h00));
                h1hi_s[g][o0 + 1] = h01;      h1lo_s[g][o0 + 1] = __float2bfloat16(v01 - __bfloat162float(h01));
                h1hi_s[g + 8][o0] = h10;      h1lo_s[g + 8][o0] = __float2bfloat16(v10 - __bfloat162float(h10));
                h1hi_s[g + 8][o0 + 1] = h11;  h1lo_s[g + 8][o0 + 1] = __float2bfloat16(v11 - __bfloat162float(h11));
            }
        }
        __syncthreads();
        // ---- phase C: layer1 (256 outputs, K=128 mma) ----
        {
            float acc[2][4];
            #pragma unroll
            for (int q = 0; q < 2; q++)
                #pragma unroll
                for (int r = 0; r < 4; r++) acc[q][r] = 0.0f;
            #pragma unroll
            for (int kt = 0; kt < 8; kt++) {
                unsigned ah0, ah1, ah2, ah3, al0, al1, al2, al3;
                LDSM4(ah0, ah1, ah2, ah3, aH1  + kt * 32);
                LDSM4(al0, al1, al2, al3, aH1l + kt * 32);
                uint4 W0q = __ldg(&g_W1Frag[((wrp * 2 + 0) * 8 + kt) * 32 + lane]);
                uint4 W1q = __ldg(&g_W1Frag[((wrp * 2 + 1) * 8 + kt) * 32 + lane]);
                MMA_BF16(acc[0], ah0, ah1, ah2, ah3, W0q.x, W0q.y);
                MMA_BF16(acc[1], ah0, ah1, ah2, ah3, W1q.x, W1q.y);
                MMA_BF16(acc[0], ah0, ah1, ah2, ah3, W0q.z, W0q.w);
                MMA_BF16(acc[1], ah0, ah1, ah2, ah3, W1q.z, W1q.w);
                MMA_BF16(acc[0], al0, al1, al2, al3, W0q.x, W0q.y);
                MMA_BF16(acc[1], al0, al1, al2, al3, W1q.x, W1q.y);
            }
            #pragma unroll
            for (int q = 0; q < 2; q++) {
                int o0 = (q == 0) ? oB0 : oB1, o1 = o0 + 1;
                float v00 = lipswish(acc[q][0] + ((q == 0) ? b100 : b110));
                float v01 = lipswish(acc[q][1] + ((q == 0) ? b101 : b111));
                float v10 = lipswish(acc[q][2] + ((q == 0) ? b100 : b110));
                float v11 = lipswish(acc[q][3] + ((q == 0) ? b101 : b111));
                __nv_bfloat16 h00 = __float2bfloat16(v00), h01 = __float2bfloat16(v01);
                __nv_bfloat16 h10 = __float2bfloat16(v10), h11 = __float2bfloat16(v11);
                if (wrp < 8) {
                    hvhi_s[g][o0] = h00;      hvlo_s[g][o0] = __float2bfloat16(v00 - __bfloat162float(h00));
                    hvhi_s[g][o1] = h01;      hvlo_s[g][o1] = __float2bfloat16(v01 - __bfloat162float(h01));
                    hvhi_s[g + 8][o0] = h10;  hvlo_s[g + 8][o0] = __float2bfloat16(v10 - __bfloat162float(h10));
                    hvhi_s[g + 8][o1] = h11;  hvlo_s[g + 8][o1] = __float2bfloat16(v11 - __bfloat162float(h11));
                } else {
                    int k0 = o0 - 128, k1 = o1 - 128;
                    Ahi_s[g][k0] = h00;       Alo_s[g][k0] = __float2bfloat16(v00 - __bfloat162float(h00));
                    Ahi_s[g][k1] = h01;       Alo_s[g][k1] = __float2bfloat16(v01 - __bfloat162float(h01));
                    Ahi_s[g + 8][k0] = h10;   Alo_s[g + 8][k0] = __float2bfloat16(v10 - __bfloat162float(h10));
                    Ahi_s[g + 8][k1] = h11;   Alo_s[g + 8][k1] = __float2bfloat16(v11 - __bfloat162float(h11));
                }
            }
        }
        __syncthreads();
        // ---- phase D: drift head (64 outputs, K=128 mma), warps 0..7; y in place ----
        if (wrp < 8) {
            float acc[4] = {0.0f, 0.0f, 0.0f, 0.0f};
            #pragma unroll
            for (int kt = 0; kt < 8; kt++) {
                unsigned ah0, ah1, ah2, ah3, al0, al1, al2, al3;
                LDSM4(ah0, ah1, ah2, ah3, aHv  + kt * 32);
                LDSM4(al0, al1, al2, al3, aHvl + kt * 32);
                uint4 W = __ldg(&g_Wv2Frag[(wrp * 8 + kt) * 32 + lane]);
                MMA_BF16(acc, ah0, ah1, ah2, ah3, W.x, W.y);
                MMA_BF16(acc, ah0, ah1, ah2, ah3, W.z, W.w);
                MMA_BF16(acc, al0, al1, al2, al3, W.x, W.y);
            }
            if (g < BT) {
                y_s[g][oD]     += sv0 * tanh_fast(acc[0] + bv20);
                y_s[g][oD + 1] += sv1 * tanh_fast(acc[1] + bv21);
            }
            if (g + 8 < BT) {
                y_s[g + 8][oD]     += sv0 * tanh_fast(acc[2] + bv20);
                y_s[g + 8][oD + 1] += sv1 * tanh_fast(acc[3] + bv21);
            }
        }
        // ---- phase E: controlled field mma (R12 2-pass shape), term-interleaved ----
        #pragma unroll 1
        for (int pass = 0; pass < 2; pass++) {
            const int h0 = wrp * 4 + pass * 2;
            float acc[2][4][4];
            #pragma unroll
            for (int hp = 0; hp < 2; hp++)
                #pragma unroll
                for (int q = 0; q < 4; q++)
                    #pragma unroll
                    for (int r = 0; r < 4; r++) acc[hp][q][r] = 0.0f;
            #pragma unroll
            for (int kt = 0; kt < 8; kt++) {
                unsigned ah0, ah1, ah2, ah3, al0, al1, al2, al3;
                LDSM4(ah0, ah1, ah2, ah3, aA  + kt * 32);
                LDSM4(al0, al1, al2, al3, aAl + kt * 32);
                uint4 W[2][4];
                #pragma unroll
                for (int hp = 0; hp < 2; hp++)
                    #pragma unroll
                    for (int q = 0; q < 4; q++)
                        W[hp][q] = __ldcg(&g_WcFrag[((((h0 + hp) * 4 + q) * 8) + kt) * 32 + lane]);
                // term 1: Ah x Wh — all 8 accumulators
                #pragma unroll
                for (int hp = 0; hp < 2; hp++)
                    #pragma unroll
                    for (int q = 0; q < 4; q++)
                        MMA_BF16(acc[hp][q], ah0, ah1, ah2, ah3, W[hp][q].x, W[hp][q].y);
                // term 2: Ah x Wl
                #pragma unroll
                for (int hp = 0; hp < 2; hp++)
                    #pragma unroll
                    for (int q = 0; q < 4; q++)
                        MMA_BF16(acc[hp][q], ah0, ah1, ah2, ah3, W[hp][q].z, W[hp][q].w);
                // term 3: Al x Wh
                #pragma unroll
                for (int hp = 0; hp < 2; hp++)
                    #pragma unroll
                    for (int q = 0; q < 4; q++)
                        MMA_BF16(acc[hp][q], al0, al1, al2, al3, W[hp][q].x, W[hp][q].y);
            }
            #pragma unroll
            for (int hp = 0; hp < 2; hp++) {
                float s0 = 0.0f, s1 = 0.0f;
                #pragma unroll
                for (int q = 0; q < 4; q++) {
                    int n0 = ((h0 + hp) * 4 + q) * 8 + 2 * t;
                    float2 sc = __ldg((const float2*)&scale_c[n0]);
                    float2 bc = __ldg((const float2*)&bc2[n0]);
                    int nz0 = n0 & 31;
                    float t0 = sc.x * tanh_fast(acc[hp][q][0] + bc.x);
                    float t1 = sc.y * tanh_fast(acc[hp][q][1] + bc.y);
                    float t2 = sc.x * tanh_fast(acc[hp][q][2] + bc.x);
                    float t3 = sc.y * tanh_fast(acc[hp][q][3] + bc.y);
                    s0 = fmaf(t0, bm_s[g][nz0],     fmaf(t1, bm_s[g][nz0 + 1],     s0));
                    s1 = fmaf(t2, bm_s[g + 8][nz0], fmaf(t3, bm_s[g + 8][nz0 + 1], s1));
                }
                s0 += __shfl_xor_sync(0xffffffffu, s0, 1);
                s0 += __shfl_xor_sync(0xffffffffu, s0, 2);
                s1 += __shfl_xor_sync(0xffffffffu, s1, 1);
                s1 += __shfl_xor_sync(0xffffffffu, s1, 2);
                if (t == 0) {
                    int h = h0 + hp;
                    diff_s[h][g] = s0;
                    if (g < 6) diff_s[h][g + 8] = s1;
                }
            }
        }
        __syncthreads();
        // ---- phase F: y += diff (strided: BT*64 = 896 > NTHR) ----
        for (int i = tid; i < BT * 64; i += NTHR) {
            int b = i >> 6, h = i & 63;
            float v = y_s[b][h] + diff_s[h][b];
            y_s[b][h] = v;
            __nv_bfloat16 hh = __float2bfloat16(v);
            yhi_s[b][h] = hh;
            ylo_s[b][h] = __float2bfloat16(v - __bfloat162float(hh));
        }
        __syncthreads();
        // ---- readout: out[b, step, :] = y @ Wr^T + br ----
        if (tid < BT * DOUT) {
            int b = tid >> 3, d = tid & 7;
            if (b < nb) {
                float acc = br[d];
                #pragma unroll 8
                for (int h = 0; h < 64; h++)
                    acc = fmaf(y_s[b][h], g_WrT[h * 8 + d], acc);
                out[(size_t)(b0g + b) * (STEPS * DOUT) + step * DOUT + d] = acc;
            }
        }
    }
}

extern "C" void kernel_launch(void* const* d_in, const int* in_sizes, int n_in,
                              void* d_out, int out_size) {
    (void)in_sizes; (void)n_in; (void)out_size;
    const float* ts         = (const float*)d_in[0];
    const float* init_noise = (const float*)d_in[1];
    const float* bm         = (const float*)d_in[2];
    const float* Wi0        = (const float*)d_in[3];
    const float* bi0        = (const float*)d_in[4];
    const float* Wi1        = (const float*)d_in[5];
    const float* bi1        = (const float*)d_in[6];
    const float* Wi2        = (const float*)d_in[7];
    const float* bi2        = (const float*)d_in[8];
    const float* scale_v    = (const float*)d_in[9];
    const float* Wv0        = (const float*)d_in[10];
    const float* bv0        = (const float*)d_in[11];
    const float* Wv1        = (const float*)d_in[12];
    const float* bv1        = (const float*)d_in[13];
    const float* Wv2        = (const float*)d_in[14];
    const float* bv2        = (const float*)d_in[15];
    const float* scale_c    = (const float*)d_in[16];
    const float* Wc0        = (const float*)d_in[17];
    const float* bc0        = (const float*)d_in[18];
    const float* Wc1        = (const float*)d_in[19];
    const float* bc1        = (const float*)d_in[20];
    const float* Wc2        = (const float*)d_in[21];
    const float* bc2        = (const float*)d_in[22];
    const float* Wr         = (const float*)d_in[23];
    const float* br         = (const float*)d_in[24];
    float* out = (float*)d_out;

    prep_kernel<<<256, 256>>>(Wi0, Wi1, Wi2, Wv0, bv0, Wv1, bv1, Wv2,
                              Wc0, bc0, Wc1, bc1, Wc2, Wr);
    sde_kernel<<<NCTA, NTHR>>>(ts, init_noise, bm, bi0, bi1, bi2,
                               scale_v, bv2, scale_c, bc2, br, out);
}

// round 17
// speedup vs baseline: 2.2812x; 1.1696x over previous
#include <cuda_runtime.h>
#include <cuda_bf16.h>
#include <cuda_fp16.h>
#include <math.h>

#define BATCH 2048
#define STEPS 64
#define HID   64
#define NZv   32
#define INZ   32
#define DOUT  8
#define BT    14
#define NTHR  512
#define NCTA  ((BATCH + BT - 1) / BT)   /* 147 */

// -------- weight scratch (filled by prep_kernel each call) ----
// B/C/D mma B-fragments: bf16 hi/lo split, [ntile][ktile][lane] = {b0h,b1h,b0l,b1l}
__device__ uint4  g_W0Frag [32 * 4 * 32];   // [Wv0|Wc0], K=64 (t col in epilogue)
__device__ uint4  g_W1Frag [32 * 8 * 32];   // [Wv1|Wc1], K=128
__device__ uint4  g_Wv2Frag[ 8 * 8 * 32];   // Wv2, K=128
// E fragments: SINGLE fp16, 2 kt per uint4: [ntile][ktpair][lane] = {b0(kt0),b1(kt0),b0(kt1),b1(kt1)}
__device__ uint4  g_WcFragH[256 * 4 * 32];
__device__ float  g_Wi0T [32  * 128];
__device__ float  g_Wi1T [128 * 128];
__device__ float  g_Wi2T [128 * 64];
__device__ float  g_w0t  [256];             // Wx0[o][0]  (t column)
__device__ float  g_b0   [256];             // [bv0 | bc0]
__device__ float  g_b1   [256];             // [bv1 | bc1]
__device__ float  g_WrT  [64 * 8];          // WrT[h][d]

__device__ __forceinline__ unsigned short bf16_hi_u(float v) {
    return __bfloat16_as_ushort(__float2bfloat16(v));
}
__device__ __forceinline__ unsigned short bf16_lo_u(float v) {
    __nv_bfloat16 h = __float2bfloat16(v);
    return __bfloat16_as_ushort(__float2bfloat16(v - __bfloat162float(h)));
}
__device__ __forceinline__ unsigned pack_h2(float a, float b) {
    return (unsigned)__half_as_ushort(__float2half_rn(a)) |
           ((unsigned)__half_as_ushort(__float2half_rn(b)) << 16);
}
__device__ __forceinline__ unsigned pack_bf2(__nv_bfloat16 a, __nv_bfloat16 b) {
    return (unsigned)__bfloat16_as_ushort(a) | ((unsigned)__bfloat16_as_ushort(b) << 16);
}

__global__ void prep_kernel(const float* __restrict__ Wi0, const float* __restrict__ Wi1,
                            const float* __restrict__ Wi2,
                            const float* __restrict__ Wv0, const float* __restrict__ bv0,
                            const float* __restrict__ Wv1, const float* __restrict__ bv1,
                            const float* __restrict__ Wv2,
                            const float* __restrict__ Wc0, const float* __restrict__ bc0,
                            const float* __restrict__ Wc1, const float* __restrict__ bc1,
                            const float* __restrict__ Wc2, const float* __restrict__ Wr) {
    int tid = blockIdx.x * blockDim.x + threadIdx.x;
    int nt  = gridDim.x * blockDim.x;
    // W0 frags (K=64, source cols shifted by 1 for the t column), bf16 hi/lo
    for (int i = tid; i < 32 * 4 * 32; i += nt) {
        int lane = i & 31, kt = (i >> 5) & 3, ntg = i >> 7;
        int o = ntg * 8 + (lane >> 2);
        int k0 = kt * 16 + 2 * (lane & 3);
        const float* row = (o < 128) ? &Wv0[o * 65] : &Wc0[(o - 128) * 65];
        float w00 = row[k0 + 1], w01 = row[k0 + 2];
        float w10 = row[k0 + 9], w11 = row[k0 + 10];
        uint4 f;
        f.x = (unsigned)bf16_hi_u(w00) | ((unsigned)bf16_hi_u(w01) << 16);
        f.y = (unsigned)bf16_hi_u(w10) | ((unsigned)bf16_hi_u(w11) << 16);
        f.z = (unsigned)bf16_lo_u(w00) | ((unsigned)bf16_lo_u(w01) << 16);
        f.w = (unsigned)bf16_lo_u(w10) | ((unsigned)bf16_lo_u(w11) << 16);
        g_W0Frag[i] = f;
    }
    // W1 frags (K=128), bf16 hi/lo
    for (int i = tid; i < 32 * 8 * 32; i += nt) {
        int lane = i & 31, kt = (i >> 5) & 7, ntg = i >> 8;
        int o = ntg * 8 + (lane >> 2);
        int k0 = kt * 16 + 2 * (lane & 3);
        const float* row = (o < 128) ? &Wv1[o * 128] : &Wc1[(o - 128) * 128];
        float w00 = row[k0], w01 = row[k0 + 1], w10 = row[k0 + 8], w11 = row[k0 + 9];
        uint4 f;
        f.x = (unsigned)bf16_hi_u(w00) | ((unsigned)bf16_hi_u(w01) << 16);
        f.y = (unsigned)bf16_hi_u(w10) | ((unsigned)bf16_hi_u(w11) << 16);
        f.z = (unsigned)bf16_lo_u(w00) | ((unsigned)bf16_lo_u(w01) << 16);
        f.w = (unsigned)bf16_lo_u(w10) | ((unsigned)bf16_lo_u(w11) << 16);
        g_W1Frag[i] = f;
    }
    // Wv2 frags (K=128, N=64), bf16 hi/lo
    for (int i = tid; i < 8 * 8 * 32; i += nt) {
        int lane = i & 31, kt = (i >> 5) & 7, ntg = i >> 8;
        int o = ntg * 8 + (lane >> 2);
        int k0 = kt * 16 + 2 * (lane & 3);
        const float* row = &Wv2[o * 128];
        float w00 = row[k0], w01 = row[k0 + 1], w10 = row[k0 + 8], w11 = row[k0 + 9];
        uint4 f;
        f.x = (unsigned)bf16_hi_u(w00) | ((unsigned)bf16_hi_u(w01) << 16);
        f.y = (unsigned)bf16_hi_u(w10) | ((unsigned)bf16_hi_u(w11) << 16);
        f.z = (unsigned)bf16_lo_u(w00) | ((unsigned)bf16_lo_u(w01) << 16);
        f.w = (unsigned)bf16_lo_u(w10) | ((unsigned)bf16_lo_u(w11) << 16);
        g_Wv2Frag[i] = f;
    }
    // Wc2 frags (K=128, N=2048): single fp16, two kt per uint4
    for (int i = tid; i < 256 * 4 * 32; i += nt) {
        int lane = i & 31, p2 = (i >> 5) & 3, ntg = i >> 7;
        int n = ntg * 8 + (lane >> 2);
        int tt = lane & 3;
        const float* wr = Wc2 + (size_t)n * 128;
        int k0a = (2 * p2) * 16 + 2 * tt;
        int k0b = (2 * p2 + 1) * 16 + 2 * tt;
        uint4 f;
        f.x = pack_h2(wr[k0a],     wr[k0a + 1]);
        f.y = pack_h2(wr[k0a + 8], wr[k0a + 9]);
        f.z = pack_h2(wr[k0b],     wr[k0b + 1]);
        f.w = pack_h2(wr[k0b + 8], wr[k0b + 9]);
        g_WcFragH[i] = f;
    }
    for (int i = tid; i < 32 * 128; i += nt) {
        int k = i >> 7, o = i & 127;
        g_Wi0T[i] = Wi0[o * 32 + k];
    }
    for (int i = tid; i < 128 * 128; i += nt) {
        int k = i >> 7, o = i & 127;
        g_Wi1T[i] = Wi1[o * 128 + k];
    }
    for (int i = tid; i < 128 * 64; i += nt) {
        int k = i >> 6, o = i & 63;
        g_Wi2T[i] = Wi2[o * 128 + k];
    }
    for (int o = tid; o < 256; o += nt) {
        const float* row = (o < 128) ? &Wv0[o * 65] : &Wc0[(o - 128) * 65];
        g_w0t[o] = row[0];
        g_b0[o] = (o < 128) ? bv0[o] : bc0[o - 128];
        g_b1[o] = (o < 128) ? bv1[o] : bc1[o - 128];
    }
    for (int i = tid; i < 64 * 8; i += nt) {
        int h = i >> 3, d = i & 7;
        g_WrT[i] = Wr[d * 64 + h];
    }
}

// fast, accurate-enough transcendentals (abs err ~1e-6)
__device__ __forceinline__ float tanh_fast(float x) {
    float e = __expf(2.0f * x);
    return 1.0f - __fdividef(2.0f, 1.0f + e);
}
__device__ __forceinline__ float lipswish(float x) {
    return 0.909f * __fdividef(x, 1.0f + __expf(-x));
}

#define LDSM4(r0, r1, r2, r3, addr) \
    asm volatile("ldmatrix.sync.aligned.m8n8.x4.shared.b16 {%0,%1,%2,%3}, [%4];" \
        : "=r"(r0), "=r"(r1), "=r"(r2), "=r"(r3) : "r"(addr))

#define MMA_BF16(d, a0, a1, a2, a3, b0, b1) \
    asm("mma.sync.aligned.m16n8k16.row.col.f32.bf16.bf16.f32 " \
        "{%0,%1,%2,%3}, {%4,%5,%6,%7}, {%8,%9}, {%0,%1,%2,%3};" \
        : "+f"(d[0]), "+f"(d[1]), "+f"(d[2]), "+f"(d[3]) \
        : "r"(a0), "r"(a1), "r"(a2), "r"(a3), "r"(b0), "r"(b1))

#define MMA_F16(d, a0, a1, a2, a3, b0, b1) \
    asm("mma.sync.aligned.m16n8k16.row.col.f32.f16.f16.f32 " \
        "{%0,%1,%2,%3}, {%4,%5,%6,%7}, {%8,%9}, {%0,%1,%2,%3};" \
        : "+f"(d[0]), "+f"(d[1]), "+f"(d[2]), "+f"(d[3]) \
        : "r"(a0), "r"(a1), "r"(a2), "r"(a3), "r"(b0), "r"(b1))

__global__ void __launch_bounds__(NTHR, 1) sde_kernel(
    const float* __restrict__ ts, const float* __restrict__ init_noise,
    const float* __restrict__ bm,
    const float* __restrict__ bi0, const float* __restrict__ bi1, const float* __restrict__ bi2,
    const float* __restrict__ scale_v, const float* __restrict__ bv2,
    const float* __restrict__ scale_c, const float* __restrict__ bc2,
    const float* __restrict__ br, float* __restrict__ out)
{
    __shared__ float y_s[BT][64];                                             // 3584 B
    __shared__ __align__(16) __nv_bfloat16 yhi_s [16][72],  ylo_s [16][72];   // 4608 B
    __shared__ __align__(16) __nv_bfloat16 h1hi_s[16][264], h1lo_s[16][264];  // 16896 B
    __shared__ __align__(16) __nv_bfloat16 hvhi_s[16][136], hvlo_s[16][136];  // 8704 B
    __shared__ __align__(16) __half        Ahi_s [16][136], Alo_s [16][136];  // 8704 B (fp16 hi/lo)
    __shared__ float diff_s[64][15];                                          // 3840 B
    __shared__ float bm_s  [16][33];                                          // 2112 B
    // total 48448 B <= 49152 B

    const int tid  = threadIdx.x;
    const int b0g  = blockIdx.x * BT;
    int nb = BATCH - b0g; if (nb > BT) nb = BT;
    const float ts0 = ts[0];

    const int lane = tid & 31;
    const int wrp  = tid >> 5;                 // 0..15
    const int t    = lane & 3;
    const int g    = lane >> 2;
    const int lrow = lane & 15;
    const int kofs = (lane & 16) ? 8 : 0;
    const unsigned aY   = (unsigned)__cvta_generic_to_shared(&yhi_s [0][0]) + (lrow * 72  + kofs) * 2;
    const unsigned aYl  = (unsigned)__cvta_generic_to_shared(&ylo_s [0][0]) + (lrow * 72  + kofs) * 2;
    const unsigned aH1  = (unsigned)__cvta_generic_to_shared(&h1hi_s[0][0]) + (lrow * 264 + kofs) * 2
                          + ((wrp < 8) ? 0 : 256);   // c-warps contract h1 cols [128,256)
    const unsigned aH1l = (unsigned)__cvta_generic_to_shared(&h1lo_s[0][0]) + (lrow * 264 + kofs) * 2
                          + ((wrp < 8) ? 0 : 256);
    const unsigned aHv  = (unsigned)__cvta_generic_to_shared(&hvhi_s[0][0]) + (lrow * 136 + kofs) * 2;
    const unsigned aHvl = (unsigned)__cvta_generic_to_shared(&hvlo_s[0][0]) + (lrow * 136 + kofs) * 2;
    const unsigned aA   = (unsigned)__cvta_generic_to_shared(&Ahi_s [0][0]) + (lrow * 136 + kofs) * 2;
    const unsigned aAl  = (unsigned)__cvta_generic_to_shared(&Alo_s [0][0]) + (lrow * 136 + kofs) * 2;

    // step-invariant per-thread epilogue constants (registers)
    const int oB0 = wrp * 16 + 2 * t;      // phase B/C q=0 columns
    const int oB1 = oB0 + 8;               // q=1 columns
    const float w0t00 = g_w0t[oB0], w0t01 = g_w0t[oB0 + 1];
    const float w0t10 = g_w0t[oB1], w0t11 = g_w0t[oB1 + 1];
    const float b000 = g_b0[oB0], b001 = g_b0[oB0 + 1];
    const float b010 = g_b0[oB1], b011 = g_b0[oB1 + 1];
    const float b100 = g_b1[oB0], b101 = g_b1[oB0 + 1];
    const float b110 = g_b1[oB1], b111 = g_b1[oB1 + 1];
    const int oD = (wrp & 7) * 8 + 2 * t;   // phase D columns (warps 0..7)
    const float bv20 = bv2[oD], bv21 = bv2[oD + 1];
    const float sv0  = scale_v[oD], sv1 = scale_v[oD + 1];

    // ---------------- initial MLP: init_noise -> y0 ----------------
    {
        float* nbuf = (float*)diff_s;   // [16][32] staging (2048 B <= 3840 B)
        for (int i = tid; i < 16 * 32; i += NTHR) {
            int b = i >> 5, z = i & 31;
            nbuf[i] = (b < nb) ? init_noise[(size_t)(b0g + b) * INZ + z] : 0.0f;
        }
        __syncthreads();
        {   // L0: 32 -> 128, relu -> h1 hi/lo (cols 0..127)
            int o = tid & 127, gg = tid >> 7;
            float acc[4];
            float bias = bi0[o];
            #pragma unroll
            for (int j = 0; j < 4; j++) acc[j] = bias;
            for (int k = 0; k < 32; k++) {
                float w = g_Wi0T[k * 128 + o];
                #pragma unroll
                for (int j = 0; j < 4; j++) acc[j] = fmaf(w, nbuf[(gg * 4 + j) * 32 + k], acc[j]);
            }
            #pragma unroll
            for (int j = 0; j < 4; j++) {
                float v = fmaxf(acc[j], 0.0f);
                __nv_bfloat16 h = __float2bfloat16(v);
                h1hi_s[gg * 4 + j][o] = h;
                h1lo_s[gg * 4 + j][o] = __float2bfloat16(v - __bfloat162float(h));
            }
        }
        __syncthreads();
        {   // L1: 128 -> 128, relu -> hv hi/lo
            int o = tid & 127, gg = tid >> 7;
            float acc[4];
            float bias = bi1[o];
            #pragma unroll
            for (int j = 0; j < 4; j++) acc[j] = bias;
            for (int k = 0; k < 128; k++) {
                float w = g_Wi1T[k * 128 + o];
                #pragma unroll
                for (int j = 0; j < 4; j++) {
                    float a = __bfloat162float(h1hi_s[gg * 4 + j][k]) +
                              __bfloat162float(h1lo_s[gg * 4 + j][k]);
                    acc[j] = fmaf(w, a, acc[j]);
                }
            }
            #pragma unroll
            for (int j = 0; j < 4; j++) {
                float v = fmaxf(acc[j], 0.0f);
                __nv_bfloat16 h = __float2bfloat16(v);
                hvhi_s[gg * 4 + j][o] = h;
                hvlo_s[gg * 4 + j][o] = __float2bfloat16(v - __bfloat162float(h));
            }
        }
        __syncthreads();
        {   // L2: 128 -> 64, identity -> y0 (fp32 + hi/lo; pad rows 14,15 zeroed)
            int o = tid & 63, gg = tid >> 6;
            float bias = bi2[o];
            float a0 = bias, a1 = bias;
            for (int k = 0; k < 128; k++) {
                float w = g_Wi2T[k * 64 + o];
                float x0 = __bfloat162float(hvhi_s[gg * 2 + 0][k]) + __bfloat162float(hvlo_s[gg * 2 + 0][k]);
                float x1 = __bfloat162float(hvhi_s[gg * 2 + 1][k]) + __bfloat162float(hvlo_s[gg * 2 + 1][k]);
                a0 = fmaf(w, x0, a0);
                a1 = fmaf(w, x1, a1);
            }
            #pragma unroll
            for (int jj = 0; jj < 2; jj++) {
                int b = gg * 2 + jj;
                float v = jj ? a1 : a0;
                if (b < BT) {
                    y_s[b][o] = v;
                    __nv_bfloat16 h = __float2bfloat16(v);
                    yhi_s[b][o] = h;
                    ylo_s[b][o] = __float2bfloat16(v - __bfloat162float(h));
                } else {
                    yhi_s[b][o] = __float2bfloat16(0.0f);
                    ylo_s[b][o] = __float2bfloat16(0.0f);
                }
            }
        }
        __syncthreads();
    }

    // ---------------- time scan ----------------
    for (int step = 0; step < STEPS; step++) {
        // stage noise (nb-guarded)
        if (tid < BT * 32) {
            int b = tid >> 5, z = tid & 31;
            bm_s[b][z] = (b < nb)
                ? bm[(size_t)(b0g + b) * (STEPS * NZv) + step * NZv + z] : 0.0f;
        }
        const float tcur = ts0 + (float)step;
        // ---- phase B: layer0 (256 outputs, K=64 bf16 3-term mma) ----
        {
            float acc[2][4];
            #pragma unroll
            for (int q = 0; q < 2; q++)
                #pragma unroll
                for (int r = 0; r < 4; r++) acc[q][r] = 0.0f;
            #pragma unroll
            for (int kt = 0; kt < 4; kt++) {
                unsigned ah0, ah1, ah2, ah3, al0, al1, al2, al3;
                LDSM4(ah0, ah1, ah2, ah3, aY  + kt * 32);
                LDSM4(al0, al1, al2, al3, aYl + kt * 32);
                uint4 W0q = __ldg(&g_W0Frag[((wrp * 2 + 0) * 4 + kt) * 32 + lane]);
                uint4 W1q = __ldg(&g_W0Frag[((wrp * 2 + 1) * 4 + kt) * 32 + lane]);
                MMA_BF16(acc[0], ah0, ah1, ah2, ah3, W0q.x, W0q.y);
                MMA_BF16(acc[1], ah0, ah1, ah2, ah3, W1q.x, W1q.y);
                MMA_BF16(acc[0], ah0, ah1, ah2, ah3, W0q.z, W0q.w);
                MMA_BF16(acc[1], ah0, ah1, ah2, ah3, W1q.z, W1q.w);
                MMA_BF16(acc[0], al0, al1, al2, al3, W0q.x, W0q.y);
                MMA_BF16(acc[1], al0, al1, al2, al3, W1q.x, W1q.y);
            }
            #pragma unroll
            for (int q = 0; q < 2; q++) {
                int o0 = (q == 0) ? oB0 : oB1;
                float bia0 = fmaf((q == 0) ? w0t00 : w0t10, tcur, (q == 0) ? b000 : b010);
                float bia1 = fmaf((q == 0) ? w0t01 : w0t11, tcur, (q == 0) ? b001 : b011);
                float v00 = lipswish(acc[q][0] + bia0);
                float v01 = lipswish(acc[q][1] + bia1);
                float v10 = lipswish(acc[q][2] + bia0);
                float v11 = lipswish(acc[q][3] + bia1);
                __nv_bfloat16 h00 = __float2bfloat16(v00), h01 = __float2bfloat16(v01);
                __nv_bfloat16 h10 = __float2bfloat16(v10), h11 = __float2bfloat16(v11);
                // paired 32-bit stores (o0 even)
                *(unsigned*)&h1hi_s[g][o0]     = pack_bf2(h00, h01);
                *(unsigned*)&h1lo_s[g][o0]     = pack_bf2(__float2bfloat16(v00 - __bfloat162float(h00)),
                                                          __float2bfloat16(v01 - __bfloat162float(h01)));
                *(unsigned*)&h1hi_s[g + 8][o0] = pack_bf2(h10, h11);
                *(unsigned*)&h1lo_s[g + 8][o0] = pack_bf2(__float2bfloat16(v10 - __bfloat162float(h10)),
                                                          __float2bfloat16(v11 - __bfloat162float(h11)));
            }
        }
        __syncthreads();
        // ---- phase C: layer1 (256 outputs, K=128 bf16 3-term mma) ----
        {
            float acc[2][4];
            #pragma unroll
            for (int q = 0; q < 2; q++)
                #pragma unroll
                for (int r = 0; r < 4; r++) acc[q][r] = 0.0f;
            #pragma unroll
            for (int kt = 0; kt < 8; kt++) {
                unsigned ah0, ah1, ah2, ah3, al0, al1, al2, al3;
                LDSM4(ah0, ah1, ah2, ah3, aH1  + kt * 32);
                LDSM4(al0, al1, al2, al3, aH1l + kt * 32);
                uint4 W0q = __ldg(&g_W1Frag[((wrp * 2 + 0) * 8 + kt) * 32 + lane]);
                uint4 W1q = __ldg(&g_W1Frag[((wrp * 2 + 1) * 8 + kt) * 32 + lane]);
                MMA_BF16(acc[0], ah0, ah1, ah2, ah3, W0q.x, W0q.y);
                MMA_BF16(acc[1], ah0, ah1, ah2, ah3, W1q.x, W1q.y);
                MMA_BF16(acc[0], ah0, ah1, ah2, ah3, W0q.z, W0q.w);
                MMA_BF16(acc[1], ah0, ah1, ah2, ah3, W1q.z, W1q.w);
                MMA_BF16(acc[0], al0, al1, al2, al3, W0q.x, W0q.y);
                MMA_BF16(acc[1], al0, al1, al2, al3, W1q.x, W1q.y);
            }
            #pragma unroll
            for (int q = 0; q < 2; q++) {
                int o0 = (q == 0) ? oB0 : oB1;
                float v00 = lipswish(acc[q][0] + ((q == 0) ? b100 : b110));
                float v01 = lipswish(acc[q][1] + ((q == 0) ? b101 : b111));
                float v10 = lipswish(acc[q][2] + ((q == 0) ? b100 : b110));
                float v11 = lipswish(acc[q][3] + ((q == 0) ? b101 : b111));
                if (wrp < 8) {   // v-half -> hv (bf16 hi/lo, paired stores)
                    __nv_bfloat16 h00 = __float2bfloat16(v00), h01 = __float2bfloat16(v01);
                    __nv_bfloat16 h10 = __float2bfloat16(v10), h11 = __float2bfloat16(v11);
                    *(unsigned*)&hvhi_s[g][o0]     = pack_bf2(h00, h01);
                    *(unsigned*)&hvlo_s[g][o0]     = pack_bf2(__float2bfloat16(v00 - __bfloat162float(h00)),
                                                              __float2bfloat16(v01 - __bfloat162float(h01)));
                    *(unsigned*)&hvhi_s[g + 8][o0] = pack_bf2(h10, h11);
                    *(unsigned*)&hvlo_s[g + 8][o0] = pack_bf2(__float2bfloat16(v10 - __bfloat162float(h10)),
                                                              __float2bfloat16(v11 - __bfloat162float(h11)));
                } else {         // c-half -> A (fp16 hi/lo, k = o-128, paired stores)
                    int k0 = o0 - 128;
                    __half f00 = __float2half_rn(v00), f01 = __float2half_rn(v01);
                    __half f10 = __float2half_rn(v10), f11 = __float2half_rn(v11);
                    *(unsigned*)&Ahi_s[g][k0]     = pack_h2(v00, v01);
                    *(unsigned*)&Alo_s[g][k0]     = pack_h2(v00 - __half2float(f00), v01 - __half2float(f01));
                    *(unsigned*)&Ahi_s[g + 8][k0] = pack_h2(v10, v11);
                    *(unsigned*)&Alo_s[g + 8][k0] = pack_h2(v10 - __half2float(f10), v11 - __half2float(f11));
                }
            }
        }
        __syncthreads();
        // ---- phase D: drift head (64 outputs, K=128 bf16 3-term mma), warps 0..7 ----
        if (wrp < 8) {
            float acc[4] = {0.0f, 0.0f, 0.0f, 0.0f};
            #pragma unroll
            for (int kt = 0; kt < 8; kt++) {
                unsigned ah0, ah1, ah2, ah3, al0, al1, al2, al3;
                LDSM4(ah0, ah1, ah2, ah3, aHv  + kt * 32);
                LDSM4(al0, al1, al2, al3, aHvl + kt * 32);
                uint4 W = __ldg(&g_Wv2Frag[(wrp * 8 + kt) * 32 + lane]);
                MMA_BF16(acc, ah0, ah1, ah2, ah3, W.x, W.y);
                MMA_BF16(acc, ah0, ah1, ah2, ah3, W.z, W.w);
                MMA_BF16(acc, al0, al1, al2, al3, W.x, W.y);
            }
            if (g < BT) {
                y_s[g][oD]     += sv0 * tanh_fast(acc[0] + bv20);
                y_s[g][oD + 1] += sv1 * tanh_fast(acc[1] + bv21);
            }
            if (g + 8 < BT) {
                y_s[g + 8][oD]     += sv0 * tanh_fast(acc[2] + bv20);
                y_s[g + 8][oD + 1] += sv1 * tanh_fast(acc[3] + bv21);
            }
        }
        // ---- phase E: controlled field, fp16 weights (single) x fp16 hi/lo activations ----
        #pragma unroll 1
        for (int pass = 0; pass < 2; pass++) {
            const int h0 = wrp * 4 + pass * 2;
            float acc[2][4][4];
            #pragma unroll
            for (int hp = 0; hp < 2; hp++)
                #pragma unroll
                for (int q = 0; q < 4; q++)
                    #pragma unroll
                    for (int r = 0; r < 4; r++) acc[hp][q][r] = 0.0f;
            uint4 W4[2][4];
            #pragma unroll
            for (int kt = 0; kt < 8; kt++) {
                if ((kt & 1) == 0) {
                    #pragma unroll
                    for (int hp = 0; hp < 2; hp++)
                        #pragma unroll
                        for (int q = 0; q < 4; q++)
                            W4[hp][q] = __ldcg(&g_WcFragH[((((h0 + hp) * 4 + q) * 4) + (kt >> 1)) * 32 + lane]);
                }
                unsigned ah0, ah1, ah2, ah3, al0, al1, al2, al3;
                LDSM4(ah0, ah1, ah2, ah3, aA  + kt * 32);
                LDSM4(al0, al1, al2, al3, aAl + kt * 32);
                #pragma unroll
                for (int hp = 0; hp < 2; hp++) {
                    #pragma unroll
                    for (int q = 0; q < 4; q++) {
                        unsigned b0 = (kt & 1) ? W4[hp][q].z : W4[hp][q].x;
                        unsigned b1 = (kt & 1) ? W4[hp][q].w : W4[hp][q].y;
                        MMA_F16(acc[hp][q], ah0, ah1, ah2, ah3, b0, b1);
                        MMA_F16(acc[hp][q], al0, al1, al2, al3, b0, b1);
                    }
                }
            }
            #pragma unroll
            for (int hp = 0; hp < 2; hp++) {
                float s0 = 0.0f, s1 = 0.0f;
                #pragma unroll
                for (int q = 0; q < 4; q++) {
                    int n0 = ((h0 + hp) * 4 + q) * 8 + 2 * t;
                    float2 sc = __ldg((const float2*)&scale_c[n0]);
                    float2 bc = __ldg((const float2*)&bc2[n0]);
                    int nz0 = n0 & 31;
                    float t0 = sc.x * tanh_fast(acc[hp][q][0] + bc.x);
                    float t1 = sc.y * tanh_fast(acc[hp][q][1] + bc.y);
                    float t2 = sc.x * tanh_fast(acc[hp][q][2] + bc.x);
                    float t3 = sc.y * tanh_fast(acc[hp][q][3] + bc.y);
                    s0 = fmaf(t0, bm_s[g][nz0],     fmaf(t1, bm_s[g][nz0 + 1],     s0));
                    s1 = fmaf(t2, bm_s[g + 8][nz0], fmaf(t3, bm_s[g + 8][nz0 + 1], s1));
                }
                s0 += __shfl_xor_sync(0xffffffffu, s0, 1);
                s0 += __shfl_xor_sync(0xffffffffu, s0, 2);
                s1 += __shfl_xor_sync(0xffffffffu, s1, 1);
                s1 += __shfl_xor_sync(0xffffffffu, s1, 2);
                if (t == 0) {
                    int h = h0 + hp;
                    diff_s[h][g] = s0;
                    if (g < 6) diff_s[h][g + 8] = s1;
                }
            }
        }
        __syncthreads();
        // ---- phase F: y += diff (strided: BT*64 = 896 > NTHR) ----
        for (int i = tid; i < BT * 64; i += NTHR) {
            int b = i >> 6, h = i & 63;
            float v = y_s[b][h] + diff_s[h][b];
            y_s[b][h] = v;
            __nv_bfloat16 hh = __float2bfloat16(v);
            yhi_s[b][h] = hh;
            ylo_s[b][h] = __float2bfloat16(v - __bfloat162float(hh));
        }
        __syncthreads();
        // ---- readout: out[b, step, :] = y @ Wr^T + br ----
        if (tid < BT * DOUT) {
            int b = tid >> 3, d = tid & 7;
            if (b < nb) {
                float acc = br[d];
                #pragma unroll 8
                for (int h = 0; h < 64; h++)
                    acc = fmaf(y_s[b][h], g_WrT[h * 8 + d], acc);
                out[(size_t)(b0g + b) * (STEPS * DOUT) + step * DOUT + d] = acc;
            }
        }
    }
}

extern "C" void kernel_launch(void* const* d_in, const int* in_sizes, int n_in,
                              void* d_out, int out_size) {
    (void)in_sizes; (void)n_in; (void)out_size;
    const float* ts         = (const float*)d_in[0];
    const float* init_noise = (const float*)d_in[1];
    const float* bm         = (const float*)d_in[2];
    const float* Wi0        = (const float*)d_in[3];
    const float* bi0        = (const float*)d_in[4];
    const float* Wi1        = (const float*)d_in[5];
    const float* bi1        = (const float*)d_in[6];
    const float* Wi2        = (const float*)d_in[7];
    const float* bi2        = (const float*)d_in[8];
    const float* scale_v    = (const float*)d_in[9];
    const float* Wv0        = (const float*)d_in[10];
    const float* bv0        = (const float*)d_in[11];
    const float* Wv1        = (const float*)d_in[12];
    const float* bv1        = (const float*)d_in[13];
    const float* Wv2        = (const float*)d_in[14];
    const float* bv2        = (const float*)d_in[15];
    const float* scale_c    = (const float*)d_in[16];
    const float* Wc0        = (const float*)d_in[17];
    const float* bc0        = (const float*)d_in[18];
    const float* Wc1        = (const float*)d_in[19];
    const float* bc1        = (const float*)d_in[20];
    const float* Wc2        = (const float*)d_in[21];
    const float* bc2        = (const float*)d_in[22];
    const float* Wr         = (const float*)d_in[23];
    const float* br         = (const float*)d_in[24];
    float* out = (float*)d_out;

    prep_kernel<<<256, 256>>>(Wi0, Wi1, Wi2, Wv0, bv0, Wv1, bv1, Wv2,
                              Wc0, bc0, Wc1, bc1, Wc2, Wr);
    sde_kernel<<<NCTA, NTHR>>>(ts, init_noise, bm, bi0, bi1, bi2,
                               scale_v, bv2, scale_c, bc2, br, out);
}